// round 1
// baseline (speedup 1.0000x reference)
#include <cuda_runtime.h>
#include <cuda_bf16.h>

#define Bb   4
#define Ss   2048
#define Dd   512
#define Hh   8
#define DKk  64
#define FFNf 2048
#define ROWS (Bb*Ss)   // 8192

// ---------------- scratch (static device globals; no allocations) -------------
__device__ float g_h[ROWS*Dd];       // ln_in(x)
__device__ float g_q[ROWS*Dd];       // [B,H,S,DK]
__device__ float g_k[ROWS*Dd];
__device__ float g_v[ROWS*Dd];
__device__ float g_attn[ROWS*Dd];    // attn out + h residual
__device__ float g_o[ROWS*Dd];       // ln1 out
__device__ float g_f[ROWS*FFNf];     // ffn hidden
__device__ float g_r[ROWS*Dd];       // pre-ln2

// ---------------- LayerNorm: one block per row ------------------------------
__global__ __launch_bounds__(256) void ln_kernel(const float* __restrict__ x,
                                                 const float* __restrict__ gam,
                                                 const float* __restrict__ bet,
                                                 float* __restrict__ out)
{
    const int row = blockIdx.x;
    const int tid = threadIdx.x;
    const float2 v = ((const float2*)(x + (size_t)row * Dd))[tid];
    float s  = v.x + v.y;
    float ss = v.x * v.x + v.y * v.y;
    #pragma unroll
    for (int o = 16; o; o >>= 1) {
        s  += __shfl_xor_sync(~0u, s,  o);
        ss += __shfl_xor_sync(~0u, ss, o);
    }
    __shared__ float rs[8], rss[8];
    if ((tid & 31) == 0) { rs[tid >> 5] = s; rss[tid >> 5] = ss; }
    __syncthreads();
    float tot = 0.f, tot2 = 0.f;
    #pragma unroll
    for (int i = 0; i < 8; i++) { tot += rs[i]; tot2 += rss[i]; }
    const float mean = tot * (1.0f / Dd);
    const float var  = tot2 * (1.0f / Dd) - mean * mean;
    const float rstd = rsqrtf(var + 1e-5f);
    const float2 g2 = ((const float2*)gam)[tid];
    const float2 b2 = ((const float2*)bet)[tid];
    float2 o;
    o.x = (v.x - mean) * rstd * g2.x + b2.x;
    o.y = (v.y - mean) * rstd * g2.y + b2.y;
    ((float2*)(out + (size_t)row * Dd))[tid] = o;
}

// ---------------- fp32 tiled GEMM: C = A[MxK] @ W[KxN] + bias (+res) --------
// MODE 0: C[m,n] = acc + bias[n]
// MODE 1: QKV scatter: write to [B,H,S,DK] layout, + bias
// MODE 2: C[m,n] = acc + bias[n] + res[m,n]
template<int MODE>
__global__ __launch_bounds__(256) void gemm_kernel(const float* __restrict__ A,
                                                   const float* __restrict__ W,
                                                   const float* __restrict__ bias,
                                                   const float* __restrict__ res,
                                                   float* __restrict__ C,
                                                   int M, int N, int K)
{
    __shared__ float As[16][128];   // transposed A tile: As[k][m]
    __shared__ float Bs[16][128];   // Bs[k][n]

    const int tid = threadIdx.x;
    const int tx = tid & 15;        // N direction (8 cols each)
    const int ty = tid >> 4;        // M direction (8 rows each)
    const int m0 = blockIdx.y * 128;
    const int n0 = blockIdx.x * 128;

    const int arow = tid >> 2;            // 0..63
    const int acol = (tid & 3) * 4;       // 0,4,8,12
    const int brow = tid >> 5;            // 0..7
    const int bcol = (tid & 31) * 4;      // 0..124

    float acc[8][8];
    #pragma unroll
    for (int i = 0; i < 8; i++)
        #pragma unroll
        for (int j = 0; j < 8; j++) acc[i][j] = 0.f;

    for (int k0 = 0; k0 < K; k0 += 16) {
        float4 a0 = *(const float4*)&A[(size_t)(m0 + arow)      * K + k0 + acol];
        float4 a1 = *(const float4*)&A[(size_t)(m0 + arow + 64) * K + k0 + acol];
        float4 b0 = *(const float4*)&W[(size_t)(k0 + brow)     * N + n0 + bcol];
        float4 b1 = *(const float4*)&W[(size_t)(k0 + brow + 8) * N + n0 + bcol];

        As[acol + 0][arow] = a0.x; As[acol + 1][arow] = a0.y;
        As[acol + 2][arow] = a0.z; As[acol + 3][arow] = a0.w;
        As[acol + 0][arow + 64] = a1.x; As[acol + 1][arow + 64] = a1.y;
        As[acol + 2][arow + 64] = a1.z; As[acol + 3][arow + 64] = a1.w;
        *(float4*)&Bs[brow][bcol]     = b0;
        *(float4*)&Bs[brow + 8][bcol] = b1;
        __syncthreads();

        #pragma unroll
        for (int k = 0; k < 16; k++) {
            float4 af0 = *(const float4*)&As[k][ty * 8];
            float4 af1 = *(const float4*)&As[k][ty * 8 + 4];
            float4 bf0 = *(const float4*)&Bs[k][tx * 8];
            float4 bf1 = *(const float4*)&Bs[k][tx * 8 + 4];
            float a[8] = {af0.x, af0.y, af0.z, af0.w, af1.x, af1.y, af1.z, af1.w};
            float b[8] = {bf0.x, bf0.y, bf0.z, bf0.w, bf1.x, bf1.y, bf1.z, bf1.w};
            #pragma unroll
            for (int i = 0; i < 8; i++)
                #pragma unroll
                for (int j = 0; j < 8; j++)
                    acc[i][j] = fmaf(a[i], b[j], acc[i][j]);
        }
        __syncthreads();
    }

    #pragma unroll
    for (int i = 0; i < 8; i++) {
        const int m = m0 + ty * 8 + i;
        #pragma unroll
        for (int j4 = 0; j4 < 2; j4++) {
            const int n = n0 + tx * 8 + j4 * 4;
            const float4 bv = *(const float4*)&bias[n];
            float4 r;
            r.x = acc[i][j4 * 4 + 0] + bv.x;
            r.y = acc[i][j4 * 4 + 1] + bv.y;
            r.z = acc[i][j4 * 4 + 2] + bv.z;
            r.w = acc[i][j4 * 4 + 3] + bv.w;
            if (MODE == 2) {
                const float4 rv = *(const float4*)&res[(size_t)m * N + n];
                r.x += rv.x; r.y += rv.y; r.z += rv.z; r.w += rv.w;
            }
            if (MODE == 1) {
                const int hh = n >> 6, d = n & 63;
                const int bidx = m >> 11, sidx = m & (Ss - 1);
                *(float4*)&C[((((size_t)bidx * Hh + hh) * Ss) + sidx) * DKk + d] = r;
            } else {
                *(float4*)&C[(size_t)m * N + n] = r;
            }
        }
    }
}

// ---------------- banded flash attention -------------------------------------
// grid: (S/128 chunks, B*H). block 128 threads; thread = one query row.
// window for chunk cs: keys in [max(0,cs-512), min(S,cs+256))
__global__ __launch_bounds__(128) void attn_kernel(const float* __restrict__ q,
                                                   const float* __restrict__ kk,
                                                   const float* __restrict__ vv,
                                                   const float* __restrict__ hin,
                                                   float* __restrict__ out)
{
    const int bh  = blockIdx.y;
    const int cs  = blockIdx.x * 128;
    const int tid = threadIdx.x;
    const int s   = cs + tid;

    __shared__ float ks[16][64];
    __shared__ float vs[16][64];

    float4 qr[16];
    {
        const float4* qp = (const float4*)(q + (((size_t)bh) * Ss + s) * DKk);
        #pragma unroll
        for (int i = 0; i < 16; i++) qr[i] = qp[i];
    }

    float acc[64];
    #pragma unroll
    for (int i = 0; i < 64; i++) acc[i] = 0.f;
    float mx = -1e30f, l = 0.f;

    int w0 = cs - 512; if (w0 < 0) w0 = 0;
    int w1 = cs + 256; if (w1 > Ss) w1 = Ss;

    for (int j0 = w0; j0 < w1; j0 += 16) {
        __syncthreads();
        const float4* kb = (const float4*)(kk + (((size_t)bh) * Ss + j0) * DKk);
        const float4* vb = (const float4*)(vv + (((size_t)bh) * Ss + j0) * DKk);
        ((float4*)ks)[tid]       = kb[tid];
        ((float4*)ks)[tid + 128] = kb[tid + 128];
        ((float4*)vs)[tid]       = vb[tid];
        ((float4*)vs)[tid + 128] = vb[tid + 128];
        __syncthreads();

        float sc[16];
        #pragma unroll
        for (int j = 0; j < 16; j++) {
            const float4* kr = (const float4*)ks[j];
            float d0 = 0.f, d1 = 0.f, d2 = 0.f, d3 = 0.f;
            #pragma unroll
            for (int i = 0; i < 16; i++) {
                const float4 kvv = kr[i];
                d0 = fmaf(qr[i].x, kvv.x, d0);
                d1 = fmaf(qr[i].y, kvv.y, d1);
                d2 = fmaf(qr[i].z, kvv.z, d2);
                d3 = fmaf(qr[i].w, kvv.w, d3);
            }
            sc[j] = (d0 + d1 + d2 + d3) * 0.125f;
        }

        float mt = mx;
        #pragma unroll
        for (int j = 0; j < 16; j++) mt = fmaxf(mt, sc[j]);
        if (mt > mx) {
            const float scale = __expf(mx - mt);
            l *= scale;
            #pragma unroll
            for (int i = 0; i < 64; i++) acc[i] *= scale;
            mx = mt;
        }

        #pragma unroll
        for (int j = 0; j < 16; j++) {
            const float p = __expf(sc[j] - mx);
            l += p;
            const float4* vr = (const float4*)vs[j];
            #pragma unroll
            for (int i = 0; i < 16; i++) {
                const float4 vvv = vr[i];
                acc[i * 4 + 0] = fmaf(p, vvv.x, acc[i * 4 + 0]);
                acc[i * 4 + 1] = fmaf(p, vvv.y, acc[i * 4 + 1]);
                acc[i * 4 + 2] = fmaf(p, vvv.z, acc[i * 4 + 2]);
                acc[i * 4 + 3] = fmaf(p, vvv.w, acc[i * 4 + 3]);
            }
        }
    }

    const float inv = 1.0f / l;
    const int b    = bh >> 3;
    const int head = bh & 7;
    const size_t base = ((size_t)b * Ss + s) * Dd + head * DKk;
    const float4* hp = (const float4*)(hin + base);
    float4* op = (float4*)(out + base);
    #pragma unroll
    for (int i = 0; i < 16; i++) {
        const float4 hv = hp[i];
        float4 o;
        o.x = acc[i * 4 + 0] * inv + hv.x;
        o.y = acc[i * 4 + 1] * inv + hv.y;
        o.z = acc[i * 4 + 2] * inv + hv.z;
        o.w = acc[i * 4 + 3] * inv + hv.w;
        op[i] = o;
    }
}

// ---------------- launch ------------------------------------------------------
extern "C" void kernel_launch(void* const* d_in, const int* in_sizes, int n_in,
                              void* d_out, int out_size)
{
    const float* x      = (const float*)d_in[0];
    // d_in[1] = mask — structural, recomputed analytically, ignored
    const float* ln_in_g = (const float*)d_in[2];
    const float* ln_in_b = (const float*)d_in[3];
    const float* wq = (const float*)d_in[4];  const float* bq = (const float*)d_in[5];
    const float* wk = (const float*)d_in[6];  const float* bk = (const float*)d_in[7];
    const float* wv = (const float*)d_in[8];  const float* bv = (const float*)d_in[9];
    const float* ln1_g = (const float*)d_in[10]; const float* ln1_b = (const float*)d_in[11];
    const float* w1 = (const float*)d_in[12]; const float* b1 = (const float*)d_in[13];
    const float* w2 = (const float*)d_in[14]; const float* b2 = (const float*)d_in[15];
    const float* ln2_g = (const float*)d_in[16]; const float* ln2_b = (const float*)d_in[17];
    float* out = (float*)d_out;

    float *ph, *pq, *pk, *pv, *pattn, *po, *pf, *pr;
    cudaGetSymbolAddress((void**)&ph,    g_h);
    cudaGetSymbolAddress((void**)&pq,    g_q);
    cudaGetSymbolAddress((void**)&pk,    g_k);
    cudaGetSymbolAddress((void**)&pv,    g_v);
    cudaGetSymbolAddress((void**)&pattn, g_attn);
    cudaGetSymbolAddress((void**)&po,    g_o);
    cudaGetSymbolAddress((void**)&pf,    g_f);
    cudaGetSymbolAddress((void**)&pr,    g_r);

    // 1. h = LN(x)
    ln_kernel<<<ROWS, 256>>>(x, ln_in_g, ln_in_b, ph);

    // 2. QKV projections (scattered to [B,H,S,DK])
    dim3 gqkv(Dd / 128, ROWS / 128);
    gemm_kernel<1><<<gqkv, 256>>>(ph, wq, bq, nullptr, pq, ROWS, Dd, Dd);
    gemm_kernel<1><<<gqkv, 256>>>(ph, wk, bk, nullptr, pk, ROWS, Dd, Dd);
    gemm_kernel<1><<<gqkv, 256>>>(ph, wv, bv, nullptr, pv, ROWS, Dd, Dd);

    // 3. banded attention + residual with h
    attn_kernel<<<dim3(Ss / 128, Bb * Hh), 128>>>(pq, pk, pv, ph, pattn);

    // 4. o = LN1(attn_out)
    ln_kernel<<<ROWS, 256>>>(pattn, ln1_g, ln1_b, po);

    // 5. FFN
    gemm_kernel<0><<<dim3(FFNf / 128, ROWS / 128), 256>>>(po, w1, b1, nullptr, pf, ROWS, FFNf, Dd);
    gemm_kernel<2><<<dim3(Dd / 128, ROWS / 128), 256>>>(pf, w2, b2, pattn, pr, ROWS, Dd, FFNf);

    // 6. out = LN2
    ln_kernel<<<ROWS, 256>>>(pr, ln2_g, ln2_b, out);
}

// round 3
// speedup vs baseline: 1.5752x; 1.5752x over previous
#include <cuda_runtime.h>
#include <cuda_bf16.h>
#include <cstdint>

#define Bb   4
#define Ss   2048
#define Dd   512
#define Hh   8
#define DKk  64
#define FFNf 2048
#define ROWS (Bb*Ss)   // 8192

// ---------------- scratch (static device globals; no allocations) -------------
__device__ float g_h[ROWS*Dd];
__device__ float g_q[ROWS*Dd];       // [B,H,S,DK]
__device__ float g_k[ROWS*Dd];
__device__ float g_v[ROWS*Dd];
__device__ float g_attn[ROWS*Dd];
__device__ float g_o[ROWS*Dd];
__device__ float g_f[ROWS*FFNf];
__device__ float g_r[ROWS*Dd];
// transposed (K-major, [N,K]) weights
__device__ float g_wqt[Dd*Dd];
__device__ float g_wkt[Dd*Dd];
__device__ float g_wvt[Dd*Dd];
__device__ float g_w1t[FFNf*Dd];
__device__ float g_w2t[Dd*FFNf];

__device__ __forceinline__ uint32_t f2tf32(float f) {
    uint32_t r; asm("cvt.rna.tf32.f32 %0, %1;" : "=r"(r) : "f"(f)); return r;
}

__device__ __forceinline__ void mma_tf32(float4& d,
                                         uint32_t a0, uint32_t a1, uint32_t a2, uint32_t a3,
                                         uint32_t b0, uint32_t b1) {
    asm volatile(
        "mma.sync.aligned.m16n8k8.row.col.f32.tf32.tf32.f32 "
        "{%0,%1,%2,%3}, {%4,%5,%6,%7}, {%8,%9}, {%0,%1,%2,%3};"
        : "+f"(d.x), "+f"(d.y), "+f"(d.z), "+f"(d.w)
        : "r"(a0), "r"(a1), "r"(a2), "r"(a3), "r"(b0), "r"(b1));
}

// ---------------- LayerNorm ---------------------------------------------------
__global__ __launch_bounds__(256) void ln_kernel(const float* __restrict__ x,
                                                 const float* __restrict__ gam,
                                                 const float* __restrict__ bet,
                                                 float* __restrict__ out)
{
    const int row = blockIdx.x;
    const int tid = threadIdx.x;
    const float2 v = ((const float2*)(x + (size_t)row * Dd))[tid];
    float s = v.x + v.y, ss = v.x * v.x + v.y * v.y;
    #pragma unroll
    for (int o = 16; o; o >>= 1) {
        s  += __shfl_xor_sync(~0u, s,  o);
        ss += __shfl_xor_sync(~0u, ss, o);
    }
    __shared__ float rs[8], rss[8];
    if ((tid & 31) == 0) { rs[tid >> 5] = s; rss[tid >> 5] = ss; }
    __syncthreads();
    float tot = 0.f, tot2 = 0.f;
    #pragma unroll
    for (int i = 0; i < 8; i++) { tot += rs[i]; tot2 += rss[i]; }
    const float mean = tot * (1.0f / Dd);
    const float var  = tot2 * (1.0f / Dd) - mean * mean;
    const float rstd = rsqrtf(var + 1e-5f);
    const float2 g2 = ((const float2*)gam)[tid];
    const float2 b2 = ((const float2*)bet)[tid];
    float2 o;
    o.x = (v.x - mean) * rstd * g2.x + b2.x;
    o.y = (v.y - mean) * rstd * g2.y + b2.y;
    ((float2*)(out + (size_t)row * Dd))[tid] = o;
}

// ---------------- weight transpose [K,N] -> [N,K] -----------------------------
__global__ __launch_bounds__(256) void transpose_kernel(const float* __restrict__ W,
                                                        float* __restrict__ Wt,
                                                        int K, int N)
{
    __shared__ float t[32][33];
    const int n0 = blockIdx.x * 32, k0 = blockIdx.y * 32;
    const int tx = threadIdx.x, ty = threadIdx.y;
    #pragma unroll
    for (int i = 0; i < 32; i += 8) t[ty + i][tx] = W[(size_t)(k0 + ty + i) * N + n0 + tx];
    __syncthreads();
    #pragma unroll
    for (int i = 0; i < 32; i += 8) Wt[(size_t)(n0 + ty + i) * K + k0 + tx] = t[tx][ty + i];
}

// ---------------- tf32 warp-MMA GEMM: C[M,N] = A[M,K] @ Bt[N,K]^T + bias ------
// MODE 0: +bias   MODE 1: +bias, scatter to [B,H,S,DK]   MODE 2: +bias+res
// CTA 128x128, k-tile 32. 8 warps: warp (w&1) -> M half (64), (w>>1) -> N quarter (32).
// smem pitch 36 floats: fragment loads (4*row + k) mod 32 -> conflict-free.
template<int MODE>
__global__ __launch_bounds__(256, 2) void mma_gemm(const float* __restrict__ A,
                                                   const float* __restrict__ Bt,
                                                   const float* __restrict__ bias,
                                                   const float* __restrict__ res,
                                                   float* __restrict__ C,
                                                   int M, int N, int K)
{
    __shared__ __align__(16) uint32_t sA[128 * 36];
    __shared__ __align__(16) uint32_t sB[128 * 36];

    const int tid  = threadIdx.x;
    const int m0   = blockIdx.y * 128;
    const int n0   = blockIdx.x * 128;
    const int w    = tid >> 5, lane = tid & 31;
    const int wm   = (w & 1) * 64;
    const int wn   = (w >> 1) * 32;
    const int r    = lane >> 2;     // 0..7
    const int c    = lane & 3;      // 0..3

    float4 acc[4][4];
    #pragma unroll
    for (int i = 0; i < 4; i++)
        #pragma unroll
        for (int j = 0; j < 4; j++) acc[i][j] = make_float4(0.f, 0.f, 0.f, 0.f);

    const int grow  = tid >> 1;          // 0..127
    const int ghalf = (tid & 1) * 16;    // 0 or 16
    const float4* ap = (const float4*)&A [(size_t)(m0 + grow) * K + ghalf];
    const float4* bp = (const float4*)&Bt[(size_t)(n0 + grow) * K + ghalf];
    uint32_t* sArow = &sA[grow * 36 + ghalf];
    uint32_t* sBrow = &sB[grow * 36 + ghalf];

    for (int k0 = 0; k0 < K; k0 += 32) {
        #pragma unroll
        for (int j = 0; j < 4; j++) {
            const float4 av = ap[j];
            const float4 bv = bp[j];
            uint4 au, bu;
            au.x = f2tf32(av.x); au.y = f2tf32(av.y); au.z = f2tf32(av.z); au.w = f2tf32(av.w);
            bu.x = f2tf32(bv.x); bu.y = f2tf32(bv.y); bu.z = f2tf32(bv.z); bu.w = f2tf32(bv.w);
            *(uint4*)(sArow + j * 4) = au;
            *(uint4*)(sBrow + j * 4) = bu;
        }
        ap += 8;
        bp += 8;
        __syncthreads();

        #pragma unroll
        for (int ks = 0; ks < 4; ks++) {
            const int kb = ks * 8 + c;
            uint32_t af[4][4];
            #pragma unroll
            for (int mt = 0; mt < 4; mt++) {
                const int mr = wm + mt * 16 + r;
                af[mt][0] = sA[mr * 36 + kb];
                af[mt][1] = sA[(mr + 8) * 36 + kb];
                af[mt][2] = sA[mr * 36 + kb + 4];
                af[mt][3] = sA[(mr + 8) * 36 + kb + 4];
            }
            uint32_t bf[4][2];
            #pragma unroll
            for (int nt = 0; nt < 4; nt++) {
                const int nr = wn + nt * 8 + r;
                bf[nt][0] = sB[nr * 36 + kb];
                bf[nt][1] = sB[nr * 36 + kb + 4];
            }
            #pragma unroll
            for (int mt = 0; mt < 4; mt++)
                #pragma unroll
                for (int nt = 0; nt < 4; nt++)
                    mma_tf32(acc[mt][nt], af[mt][0], af[mt][1], af[mt][2], af[mt][3],
                             bf[nt][0], bf[nt][1]);
        }
        __syncthreads();
    }

    // epilogue: c0,c1 -> (m, n..n+1); c2,c3 -> (m+8, n..n+1)
    #pragma unroll
    for (int mt = 0; mt < 4; mt++) {
        #pragma unroll
        for (int nt = 0; nt < 4; nt++) {
            const int m = m0 + wm + mt * 16 + r;
            const int n = n0 + wn + nt * 8 + c * 2;
            const float2 bv = *(const float2*)&bias[n];
            float2 lo, hi;
            lo.x = acc[mt][nt].x + bv.x;  lo.y = acc[mt][nt].y + bv.y;
            hi.x = acc[mt][nt].z + bv.x;  hi.y = acc[mt][nt].w + bv.y;
            if (MODE == 2) {
                const float2 r0 = *(const float2*)&res[(size_t)m * N + n];
                const float2 r1 = *(const float2*)&res[(size_t)(m + 8) * N + n];
                lo.x += r0.x; lo.y += r0.y;
                hi.x += r1.x; hi.y += r1.y;
            }
            if (MODE == 1) {
                const int hh = n >> 6, d = n & 63;
                const int b0i = m >> 11, s0 = m & (Ss - 1);
                const int b1i = (m + 8) >> 11, s1 = (m + 8) & (Ss - 1);
                *(float2*)&C[((((size_t)b0i * Hh + hh) * Ss) + s0) * DKk + d] = lo;
                *(float2*)&C[((((size_t)b1i * Hh + hh) * Ss) + s1) * DKk + d] = hi;
            } else {
                *(float2*)&C[(size_t)m * N + n]       = lo;
                *(float2*)&C[(size_t)(m + 8) * N + n] = hi;
            }
        }
    }
}

// ---------------- banded flash attention --------------------------------------
__global__ __launch_bounds__(128) void attn_kernel(const float* __restrict__ q,
                                                   const float* __restrict__ kk,
                                                   const float* __restrict__ vv,
                                                   const float* __restrict__ hin,
                                                   float* __restrict__ out)
{
    const int bh  = blockIdx.y;
    const int cs  = blockIdx.x * 128;
    const int tid = threadIdx.x;
    const int s   = cs + tid;

    __shared__ float ks[16][64];
    __shared__ float vs[16][64];

    float4 qr[16];
    {
        const float4* qp = (const float4*)(q + (((size_t)bh) * Ss + s) * DKk);
        #pragma unroll
        for (int i = 0; i < 16; i++) qr[i] = qp[i];
    }

    float acc[64];
    #pragma unroll
    for (int i = 0; i < 64; i++) acc[i] = 0.f;
    float mx = -1e30f, l = 0.f;

    int w0 = cs - 512; if (w0 < 0) w0 = 0;
    int w1 = cs + 256; if (w1 > Ss) w1 = Ss;

    for (int j0 = w0; j0 < w1; j0 += 16) {
        __syncthreads();
        const float4* kb = (const float4*)(kk + (((size_t)bh) * Ss + j0) * DKk);
        const float4* vb = (const float4*)(vv + (((size_t)bh) * Ss + j0) * DKk);
        ((float4*)ks)[tid]       = kb[tid];
        ((float4*)ks)[tid + 128] = kb[tid + 128];
        ((float4*)vs)[tid]       = vb[tid];
        ((float4*)vs)[tid + 128] = vb[tid + 128];
        __syncthreads();

        float sc[16];
        #pragma unroll
        for (int j = 0; j < 16; j++) {
            const float4* kr = (const float4*)ks[j];
            float d0 = 0.f, d1 = 0.f, d2 = 0.f, d3 = 0.f;
            #pragma unroll
            for (int i = 0; i < 16; i++) {
                const float4 kvv = kr[i];
                d0 = fmaf(qr[i].x, kvv.x, d0);
                d1 = fmaf(qr[i].y, kvv.y, d1);
                d2 = fmaf(qr[i].z, kvv.z, d2);
                d3 = fmaf(qr[i].w, kvv.w, d3);
            }
            sc[j] = (d0 + d1 + d2 + d3) * 0.125f;
        }

        float mt = mx;
        #pragma unroll
        for (int j = 0; j < 16; j++) mt = fmaxf(mt, sc[j]);
        if (mt > mx) {
            const float scale = __expf(mx - mt);
            l *= scale;
            #pragma unroll
            for (int i = 0; i < 64; i++) acc[i] *= scale;
            mx = mt;
        }

        #pragma unroll
        for (int j = 0; j < 16; j++) {
            const float p = __expf(sc[j] - mx);
            l += p;
            const float4* vr = (const float4*)vs[j];
            #pragma unroll
            for (int i = 0; i < 16; i++) {
                const float4 vvv = vr[i];
                acc[i * 4 + 0] = fmaf(p, vvv.x, acc[i * 4 + 0]);
                acc[i * 4 + 1] = fmaf(p, vvv.y, acc[i * 4 + 1]);
                acc[i * 4 + 2] = fmaf(p, vvv.z, acc[i * 4 + 2]);
                acc[i * 4 + 3] = fmaf(p, vvv.w, acc[i * 4 + 3]);
            }
        }
    }

    const float inv = 1.0f / l;
    const int b    = bh >> 3;
    const int head = bh & 7;
    const size_t base = ((size_t)b * Ss + s) * Dd + head * DKk;
    const float4* hp = (const float4*)(hin + base);
    float4* op = (float4*)(out + base);
    #pragma unroll
    for (int i = 0; i < 16; i++) {
        const float4 hv = hp[i];
        float4 o;
        o.x = acc[i * 4 + 0] * inv + hv.x;
        o.y = acc[i * 4 + 1] * inv + hv.y;
        o.z = acc[i * 4 + 2] * inv + hv.z;
        o.w = acc[i * 4 + 3] * inv + hv.w;
        op[i] = o;
    }
}

// ---------------- launch --------------------------------------------------------
extern "C" void kernel_launch(void* const* d_in, const int* in_sizes, int n_in,
                              void* d_out, int out_size)
{
    const float* x       = (const float*)d_in[0];
    const float* ln_in_g = (const float*)d_in[2];
    const float* ln_in_b = (const float*)d_in[3];
    const float* wq = (const float*)d_in[4];  const float* bq = (const float*)d_in[5];
    const float* wk = (const float*)d_in[6];  const float* bk = (const float*)d_in[7];
    const float* wv = (const float*)d_in[8];  const float* bv = (const float*)d_in[9];
    const float* ln1_g = (const float*)d_in[10]; const float* ln1_b = (const float*)d_in[11];
    const float* w1 = (const float*)d_in[12]; const float* b1 = (const float*)d_in[13];
    const float* w2 = (const float*)d_in[14]; const float* b2 = (const float*)d_in[15];
    const float* ln2_g = (const float*)d_in[16]; const float* ln2_b = (const float*)d_in[17];
    float* out = (float*)d_out;

    float *ph, *pq, *pk, *pv, *pattn, *po, *pf, *pr;
    float *pwqt, *pwkt, *pwvt, *pw1t, *pw2t;
    cudaGetSymbolAddress((void**)&ph,    g_h);
    cudaGetSymbolAddress((void**)&pq,    g_q);
    cudaGetSymbolAddress((void**)&pk,    g_k);
    cudaGetSymbolAddress((void**)&pv,    g_v);
    cudaGetSymbolAddress((void**)&pattn, g_attn);
    cudaGetSymbolAddress((void**)&po,    g_o);
    cudaGetSymbolAddress((void**)&pf,    g_f);
    cudaGetSymbolAddress((void**)&pr,    g_r);
    cudaGetSymbolAddress((void**)&pwqt,  g_wqt);
    cudaGetSymbolAddress((void**)&pwkt,  g_wkt);
    cudaGetSymbolAddress((void**)&pwvt,  g_wvt);
    cudaGetSymbolAddress((void**)&pw1t,  g_w1t);
    cudaGetSymbolAddress((void**)&pw2t,  g_w2t);

    // weight transposes to K-major
    dim3 tb(32, 8);
    transpose_kernel<<<dim3(Dd / 32, Dd / 32), tb>>>(wq, pwqt, Dd, Dd);
    transpose_kernel<<<dim3(Dd / 32, Dd / 32), tb>>>(wk, pwkt, Dd, Dd);
    transpose_kernel<<<dim3(Dd / 32, Dd / 32), tb>>>(wv, pwvt, Dd, Dd);
    transpose_kernel<<<dim3(FFNf / 32, Dd / 32), tb>>>(w1, pw1t, Dd, FFNf);
    transpose_kernel<<<dim3(Dd / 32, FFNf / 32), tb>>>(w2, pw2t, FFNf, Dd);

    // 1. h = LN(x)
    ln_kernel<<<ROWS, 256>>>(x, ln_in_g, ln_in_b, ph);

    // 2. QKV projections via tf32 warp-MMA
    dim3 gqkv(Dd / 128, ROWS / 128);
    mma_gemm<1><<<gqkv, 256>>>(ph, pwqt, bq, nullptr, pq, ROWS, Dd, Dd);
    mma_gemm<1><<<gqkv, 256>>>(ph, pwkt, bk, nullptr, pk, ROWS, Dd, Dd);
    mma_gemm<1><<<gqkv, 256>>>(ph, pwvt, bv, nullptr, pv, ROWS, Dd, Dd);

    // 3. banded attention + residual with h
    attn_kernel<<<dim3(Ss / 128, Bb * Hh), 128>>>(pq, pk, pv, ph, pattn);

    // 4. o = LN1(attn_out)
    ln_kernel<<<ROWS, 256>>>(pattn, ln1_g, ln1_b, po);

    // 5. FFN via tf32 warp-MMA
    mma_gemm<0><<<dim3(FFNf / 128, ROWS / 128), 256>>>(po, pw1t, b1, nullptr, pf, ROWS, FFNf, Dd);
    mma_gemm<2><<<dim3(Dd / 128, ROWS / 128), 256>>>(pf, pw2t, b2, pattn, pr, ROWS, Dd, FFNf);

    // 6. out = LN2
    ln_kernel<<<ROWS, 256>>>(pr, ln2_g, ln2_b, out);
}

// round 4
// speedup vs baseline: 2.0822x; 1.3219x over previous
#include <cuda_runtime.h>
#include <cuda_fp16.h>
#include <cstdint>

#define Bb   4
#define Ss   2048
#define Dd   512
#define Hh   8
#define DKk  64
#define FFNf 2048
#define ROWS (Bb*Ss)   // 8192
#define PW   20        // smem word pitch (conflict-free: (20r+c) mod 32 all distinct)
#define STAGE_WORDS (128*PW)
#define STAGE_BYTES (STAGE_WORDS*4)

// ---------------- scratch -------------------------------------------------------
__device__ float  g_h[ROWS*Dd];
__device__ __half g_h16[ROWS*Dd];
__device__ float  g_qkv[3*ROWS*Dd];        // [3][B,H,S,DK]
__device__ float  g_attn[ROWS*Dd];
__device__ float  g_lnscratch[ROWS*Dd];
__device__ __half g_o16[ROWS*Dd];
__device__ __half g_f16[ROWS*FFNf];
__device__ float  g_r[ROWS*Dd];
__device__ __half g_wqkvt[3*Dd*Dd];        // stacked [1536, 512] K-major
__device__ __half g_w1t[FFNf*Dd];
__device__ __half g_w2t[Dd*FFNf];
__device__ float  g_bqkv[3*Dd];

// ---------------- helpers -------------------------------------------------------
__device__ __forceinline__ uint32_t smem_u32(const void* p) {
    uint32_t a;
    asm("{ .reg .u64 t; cvta.to.shared.u64 t, %1; cvt.u32.u64 %0, t; }" : "=r"(a) : "l"(p));
    return a;
}
#define CP16(dst, src)  asm volatile("cp.async.ca.shared.global [%0], [%1], 16;" :: "r"(dst), "l"(src) : "memory")
#define CP_COMMIT()     asm volatile("cp.async.commit_group;" ::: "memory")
#define CP_WAIT1()      asm volatile("cp.async.wait_group 1;" ::: "memory")

__device__ __forceinline__ void mma16(float4& d,
                                      uint32_t a0, uint32_t a1, uint32_t a2, uint32_t a3,
                                      uint32_t b0, uint32_t b1) {
    asm volatile(
        "mma.sync.aligned.m16n8k16.row.col.f32.f16.f16.f32 "
        "{%0,%1,%2,%3}, {%4,%5,%6,%7}, {%8,%9}, {%0,%1,%2,%3};"
        : "+f"(d.x), "+f"(d.y), "+f"(d.z), "+f"(d.w)
        : "r"(a0), "r"(a1), "r"(a2), "r"(a3), "r"(b0), "r"(b1));
}

// ---------------- LayerNorm (fp32 + fp16 outputs) --------------------------------
__global__ __launch_bounds__(256) void ln_kernel(const float* __restrict__ x,
                                                 const float* __restrict__ gam,
                                                 const float* __restrict__ bet,
                                                 float* __restrict__ out32,
                                                 __half* __restrict__ out16)
{
    const int row = blockIdx.x;
    const int tid = threadIdx.x;
    const float2 v = ((const float2*)(x + (size_t)row * Dd))[tid];
    float s = v.x + v.y, ss = v.x * v.x + v.y * v.y;
    #pragma unroll
    for (int o = 16; o; o >>= 1) {
        s  += __shfl_xor_sync(~0u, s,  o);
        ss += __shfl_xor_sync(~0u, ss, o);
    }
    __shared__ float rs[8], rss[8];
    if ((tid & 31) == 0) { rs[tid >> 5] = s; rss[tid >> 5] = ss; }
    __syncthreads();
    float tot = 0.f, tot2 = 0.f;
    #pragma unroll
    for (int i = 0; i < 8; i++) { tot += rs[i]; tot2 += rss[i]; }
    const float mean = tot * (1.0f / Dd);
    const float var  = tot2 * (1.0f / Dd) - mean * mean;
    const float rstd = rsqrtf(var + 1e-5f);
    const float2 g2 = ((const float2*)gam)[tid];
    const float2 b2 = ((const float2*)bet)[tid];
    float2 o;
    o.x = (v.x - mean) * rstd * g2.x + b2.x;
    o.y = (v.y - mean) * rstd * g2.y + b2.y;
    ((float2*)(out32 + (size_t)row * Dd))[tid] = o;
    ((__half2*)(out16 + (size_t)row * Dd))[tid] = __floats2half2_rn(o.x, o.y);
}

// ---------------- weight transpose [K,N] -> fp16 [N,K] ---------------------------
__global__ __launch_bounds__(256) void transpose_kernel(const float* __restrict__ W,
                                                        __half* __restrict__ Wt,
                                                        int K, int N)
{
    __shared__ float t[32][33];
    const int n0 = blockIdx.x * 32, k0 = blockIdx.y * 32;
    const int tx = threadIdx.x, ty = threadIdx.y;
    #pragma unroll
    for (int i = 0; i < 32; i += 8) t[ty + i][tx] = W[(size_t)(k0 + ty + i) * N + n0 + tx];
    __syncthreads();
    #pragma unroll
    for (int i = 0; i < 32; i += 8)
        Wt[(size_t)(n0 + ty + i) * K + k0 + tx] = __float2half_rn(t[tx][ty + i]);
}

__global__ void pack_bias(const float* __restrict__ bq, const float* __restrict__ bk,
                          const float* __restrict__ bv, float* __restrict__ o)
{
    const int i = blockIdx.x * 256 + threadIdx.x;
    if (i < 512) o[i] = bq[i];
    else if (i < 1024) o[i] = bk[i - 512];
    else if (i < 1536) o[i] = bv[i - 1024];
}

// ---------------- fp16 warp-MMA GEMM, 2-stage cp.async pipeline ------------------
// C[M,N] = A[M,K](fp16) @ Bt[N,K](fp16)^T + bias
// MODE 0: write fp16 C16        MODE 1: qkv scatter (N=1536) fp32
// MODE 2: fp32 C = acc + bias + res
template<int MODE>
__global__ __launch_bounds__(256, 2) void mma_gemm(const __half* __restrict__ A,
                                                   const __half* __restrict__ Bt,
                                                   const float* __restrict__ bias,
                                                   const float* __restrict__ res,
                                                   float* __restrict__ C,
                                                   __half* __restrict__ C16,
                                                   int M, int N, int K)
{
    __shared__ __align__(16) uint32_t sA[2][STAGE_WORDS];
    __shared__ __align__(16) uint32_t sB[2][STAGE_WORDS];

    const int tid  = threadIdx.x;
    const int m0   = blockIdx.y * 128;
    const int n0   = blockIdx.x * 128;
    const int w    = tid >> 5, lane = tid & 31;
    const int wm   = (w & 1) * 64;
    const int wn   = (w >> 1) * 32;
    const int r    = lane >> 2;
    const int c    = lane & 3;

    float4 acc[4][4];
    #pragma unroll
    for (int i = 0; i < 4; i++)
        #pragma unroll
        for (int j = 0; j < 4; j++) acc[i][j] = make_float4(0.f, 0.f, 0.f, 0.f);

    const uint32_t sAbase = smem_u32(sA);
    const uint32_t sBbase = smem_u32(sB);
    const int lrow = tid >> 1;          // 0..127
    const int lsel = tid & 1;           // half-row (16 halfs = 32B)
    const uint32_t ldst_off = (uint32_t)(lrow * PW + lsel * 8) * 4;
    const __half* asrc = A  + (size_t)(m0 + lrow) * K + lsel * 16;
    const __half* bsrc = Bt + (size_t)(n0 + lrow) * K + lsel * 16;

    const int T = K >> 5;

    // prefetch stages 0,1
    #pragma unroll
    for (int p = 0; p < 2; p++) {
        const uint32_t ad = sAbase + p * STAGE_BYTES + ldst_off;
        const uint32_t bd = sBbase + p * STAGE_BYTES + ldst_off;
        const __half* as = asrc + p * 32;
        const __half* bs = bsrc + p * 32;
        CP16(ad, as); CP16(ad + 16, as + 8);
        CP16(bd, bs); CP16(bd + 16, bs + 8);
        CP_COMMIT();
    }

    for (int t = 0; t < T; t++) {
        CP_WAIT1();
        __syncthreads();
        const int buf = t & 1;
        const uint32_t* sAb = sA[buf];
        const uint32_t* sBb = sB[buf];

        #pragma unroll
        for (int kg = 0; kg < 2; kg++) {
            const int kwb = kg * 8 + c;
            uint32_t af[4][4];
            #pragma unroll
            for (int mt = 0; mt < 4; mt++) {
                const int mr = wm + mt * 16 + r;
                af[mt][0] = sAb[mr * PW + kwb];
                af[mt][1] = sAb[(mr + 8) * PW + kwb];
                af[mt][2] = sAb[mr * PW + kwb + 4];
                af[mt][3] = sAb[(mr + 8) * PW + kwb + 4];
            }
            uint32_t bf[4][2];
            #pragma unroll
            for (int nt = 0; nt < 4; nt++) {
                const int nr = wn + nt * 8 + r;
                bf[nt][0] = sBb[nr * PW + kwb];
                bf[nt][1] = sBb[nr * PW + kwb + 4];
            }
            #pragma unroll
            for (int mt = 0; mt < 4; mt++)
                #pragma unroll
                for (int nt = 0; nt < 4; nt++)
                    mma16(acc[mt][nt], af[mt][0], af[mt][1], af[mt][2], af[mt][3],
                          bf[nt][0], bf[nt][1]);
        }
        __syncthreads();

        if (t + 2 < T) {
            const uint32_t ad = sAbase + buf * STAGE_BYTES + ldst_off;
            const uint32_t bd = sBbase + buf * STAGE_BYTES + ldst_off;
            const __half* as = asrc + (t + 2) * 32;
            const __half* bs = bsrc + (t + 2) * 32;
            CP16(ad, as); CP16(ad + 16, as + 8);
            CP16(bd, bs); CP16(bd + 16, bs + 8);
        }
        CP_COMMIT();
    }

    // epilogue: d0,d1 -> (m, n, n+1); d2,d3 -> (m+8, n, n+1)
    #pragma unroll
    for (int mt = 0; mt < 4; mt++) {
        #pragma unroll
        for (int nt = 0; nt < 4; nt++) {
            const int m = m0 + wm + mt * 16 + r;
            const int n = n0 + wn + nt * 8 + c * 2;
            const float2 bv = *(const float2*)&bias[n];
            float2 lo, hi;
            lo.x = acc[mt][nt].x + bv.x;  lo.y = acc[mt][nt].y + bv.y;
            hi.x = acc[mt][nt].z + bv.x;  hi.y = acc[mt][nt].w + bv.y;
            if (MODE == 2) {
                const float2 r0 = *(const float2*)&res[(size_t)m * N + n];
                const float2 r1 = *(const float2*)&res[(size_t)(m + 8) * N + n];
                lo.x += r0.x; lo.y += r0.y;
                hi.x += r1.x; hi.y += r1.y;
            }
            if (MODE == 1) {
                const int which = n >> 9;
                const int nn = n & 511;
                const int hh = nn >> 6, d = nn & 63;
                const int b0i = m >> 11, s0 = m & (Ss - 1);
                const int b1i = (m + 8) >> 11, s1 = (m + 8) & (Ss - 1);
                float* base = C + (size_t)which * ROWS * Dd;
                *(float2*)&base[((((size_t)b0i * Hh + hh) * Ss) + s0) * DKk + d] = lo;
                *(float2*)&base[((((size_t)b1i * Hh + hh) * Ss) + s1) * DKk + d] = hi;
            } else if (MODE == 0) {
                *(__half2*)&C16[(size_t)m * N + n]       = __floats2half2_rn(lo.x, lo.y);
                *(__half2*)&C16[(size_t)(m + 8) * N + n] = __floats2half2_rn(hi.x, hi.y);
            } else {
                *(float2*)&C[(size_t)m * N + n]       = lo;
                *(float2*)&C[(size_t)(m + 8) * N + n] = hi;
            }
        }
    }
}

// ---------------- banded flash attention -----------------------------------------
__global__ __launch_bounds__(128) void attn_kernel(const float* __restrict__ q,
                                                   const float* __restrict__ kk,
                                                   const float* __restrict__ vv,
                                                   const float* __restrict__ hin,
                                                   float* __restrict__ out)
{
    const int bh  = blockIdx.y;
    const int cs  = blockIdx.x * 128;
    const int tid = threadIdx.x;
    const int s   = cs + tid;

    __shared__ float ks[16][64];
    __shared__ float vs[16][64];

    float4 qr[16];
    {
        const float4* qp = (const float4*)(q + (((size_t)bh) * Ss + s) * DKk);
        #pragma unroll
        for (int i = 0; i < 16; i++) qr[i] = qp[i];
    }

    float acc[64];
    #pragma unroll
    for (int i = 0; i < 64; i++) acc[i] = 0.f;
    float mx = -1e30f, l = 0.f;

    int w0 = cs - 512; if (w0 < 0) w0 = 0;
    int w1 = cs + 256; if (w1 > Ss) w1 = Ss;

    for (int j0 = w0; j0 < w1; j0 += 16) {
        __syncthreads();
        const float4* kb = (const float4*)(kk + (((size_t)bh) * Ss + j0) * DKk);
        const float4* vb = (const float4*)(vv + (((size_t)bh) * Ss + j0) * DKk);
        ((float4*)ks)[tid]       = kb[tid];
        ((float4*)ks)[tid + 128] = kb[tid + 128];
        ((float4*)vs)[tid]       = vb[tid];
        ((float4*)vs)[tid + 128] = vb[tid + 128];
        __syncthreads();

        float sc[16];
        #pragma unroll
        for (int j = 0; j < 16; j++) {
            const float4* kr = (const float4*)ks[j];
            float d0 = 0.f, d1 = 0.f, d2 = 0.f, d3 = 0.f;
            #pragma unroll
            for (int i = 0; i < 16; i++) {
                const float4 kvv = kr[i];
                d0 = fmaf(qr[i].x, kvv.x, d0);
                d1 = fmaf(qr[i].y, kvv.y, d1);
                d2 = fmaf(qr[i].z, kvv.z, d2);
                d3 = fmaf(qr[i].w, kvv.w, d3);
            }
            sc[j] = (d0 + d1 + d2 + d3) * 0.125f;
        }

        float mt = mx;
        #pragma unroll
        for (int j = 0; j < 16; j++) mt = fmaxf(mt, sc[j]);
        if (mt > mx) {
            const float scale = __expf(mx - mt);
            l *= scale;
            #pragma unroll
            for (int i = 0; i < 64; i++) acc[i] *= scale;
            mx = mt;
        }

        #pragma unroll
        for (int j = 0; j < 16; j++) {
            const float p = __expf(sc[j] - mx);
            l += p;
            const float4* vr = (const float4*)vs[j];
            #pragma unroll
            for (int i = 0; i < 16; i++) {
                const float4 vvv = vr[i];
                acc[i * 4 + 0] = fmaf(p, vvv.x, acc[i * 4 + 0]);
                acc[i * 4 + 1] = fmaf(p, vvv.y, acc[i * 4 + 1]);
                acc[i * 4 + 2] = fmaf(p, vvv.z, acc[i * 4 + 2]);
                acc[i * 4 + 3] = fmaf(p, vvv.w, acc[i * 4 + 3]);
            }
        }
    }

    const float inv = 1.0f / l;
    const int b    = bh >> 3;
    const int head = bh & 7;
    const size_t base = ((size_t)b * Ss + s) * Dd + head * DKk;
    const float4* hp = (const float4*)(hin + base);
    float4* op = (float4*)(out + base);
    #pragma unroll
    for (int i = 0; i < 16; i++) {
        const float4 hv = hp[i];
        float4 o;
        o.x = acc[i * 4 + 0] * inv + hv.x;
        o.y = acc[i * 4 + 1] * inv + hv.y;
        o.z = acc[i * 4 + 2] * inv + hv.z;
        o.w = acc[i * 4 + 3] * inv + hv.w;
        op[i] = o;
    }
}

// ---------------- launch ----------------------------------------------------------
extern "C" void kernel_launch(void* const* d_in, const int* in_sizes, int n_in,
                              void* d_out, int out_size)
{
    const float* x       = (const float*)d_in[0];
    const float* ln_in_g = (const float*)d_in[2];
    const float* ln_in_b = (const float*)d_in[3];
    const float* wq = (const float*)d_in[4];  const float* bq = (const float*)d_in[5];
    const float* wk = (const float*)d_in[6];  const float* bk = (const float*)d_in[7];
    const float* wv = (const float*)d_in[8];  const float* bv = (const float*)d_in[9];
    const float* ln1_g = (const float*)d_in[10]; const float* ln1_b = (const float*)d_in[11];
    const float* w1 = (const float*)d_in[12]; const float* b1 = (const float*)d_in[13];
    const float* w2 = (const float*)d_in[14]; const float* b2 = (const float*)d_in[15];
    const float* ln2_g = (const float*)d_in[16]; const float* ln2_b = (const float*)d_in[17];
    float* out = (float*)d_out;

    float *ph, *pqkv, *pattn, *plns, *pr, *pbqkv;
    __half *ph16, *po16, *pf16, *pwqkvt, *pw1t, *pw2t;
    cudaGetSymbolAddress((void**)&ph,     g_h);
    cudaGetSymbolAddress((void**)&ph16,   g_h16);
    cudaGetSymbolAddress((void**)&pqkv,   g_qkv);
    cudaGetSymbolAddress((void**)&pattn,  g_attn);
    cudaGetSymbolAddress((void**)&plns,   g_lnscratch);
    cudaGetSymbolAddress((void**)&po16,   g_o16);
    cudaGetSymbolAddress((void**)&pf16,   g_f16);
    cudaGetSymbolAddress((void**)&pr,     g_r);
    cudaGetSymbolAddress((void**)&pwqkvt, g_wqkvt);
    cudaGetSymbolAddress((void**)&pw1t,   g_w1t);
    cudaGetSymbolAddress((void**)&pw2t,   g_w2t);
    cudaGetSymbolAddress((void**)&pbqkv,  g_bqkv);

    // weight transposes (fp16, K-major); QKV stacked along N
    dim3 tb(32, 8);
    transpose_kernel<<<dim3(Dd / 32, Dd / 32), tb>>>(wq, pwqkvt, Dd, Dd);
    transpose_kernel<<<dim3(Dd / 32, Dd / 32), tb>>>(wk, pwqkvt + Dd * Dd, Dd, Dd);
    transpose_kernel<<<dim3(Dd / 32, Dd / 32), tb>>>(wv, pwqkvt + 2 * Dd * Dd, Dd, Dd);
    transpose_kernel<<<dim3(FFNf / 32, Dd / 32), tb>>>(w1, pw1t, Dd, FFNf);
    transpose_kernel<<<dim3(Dd / 32, FFNf / 32), tb>>>(w2, pw2t, FFNf, Dd);
    pack_bias<<<6, 256>>>(bq, bk, bv, pbqkv);

    // 1. h = LN(x)  (fp32 + fp16)
    ln_kernel<<<ROWS, 256>>>(x, ln_in_g, ln_in_b, ph, ph16);

    // 2. fused QKV projection (N=1536), scatter to [3][B,H,S,DK]
    mma_gemm<1><<<dim3(12, 64), 256>>>(ph16, pwqkvt, pbqkv, nullptr, pqkv, nullptr,
                                       ROWS, 3 * Dd, Dd);

    // 3. banded attention + residual h
    attn_kernel<<<dim3(Ss / 128, Bb * Hh), 128>>>(pqkv, pqkv + (size_t)ROWS * Dd,
                                                  pqkv + 2 * (size_t)ROWS * Dd, ph, pattn);

    // 4. LN1 -> fp16 (fp32 copy unused)
    ln_kernel<<<ROWS, 256>>>(pattn, ln1_g, ln1_b, plns, po16);

    // 5. FFN
    mma_gemm<0><<<dim3(FFNf / 128, 64), 256>>>(po16, pw1t, b1, nullptr, nullptr, pf16,
                                               ROWS, FFNf, Dd);
    mma_gemm<2><<<dim3(Dd / 128, 64), 256>>>(pf16, pw2t, b2, pattn, pr, nullptr,
                                             ROWS, Dd, FFNf);

    // 6. out = LN2 (fp16 copy goes to scratch)
    ln_kernel<<<ROWS, 256>>>(pr, ln2_g, ln2_b, out, ph16);
}

// round 5
// speedup vs baseline: 4.7839x; 2.2975x over previous
#include <cuda_runtime.h>
#include <cuda_fp16.h>
#include <cstdint>

#define Bb   4
#define Ss   2048
#define Dd   512
#define Hh   8
#define DKk  64
#define FFNf 2048
#define ROWS (Bb*Ss)   // 8192
#define PW   20        // gemm smem word pitch
#define STAGE_WORDS (128*PW)
#define STAGE_BYTES (STAGE_WORDS*4)
#define KVP  72        // attn K/V smem pitch in halves (144B rows)

// ---------------- scratch -------------------------------------------------------
__device__ float  g_h[ROWS*Dd];
__device__ __half g_h16[ROWS*Dd];
__device__ __half g_qkv16[3*ROWS*Dd];      // fp16 [3][B,H,S,DK]
__device__ float  g_attn[ROWS*Dd];
__device__ float  g_lnscratch[ROWS*Dd];
__device__ __half g_o16[ROWS*Dd];
__device__ __half g_f16[ROWS*FFNf];
__device__ float  g_r[ROWS*Dd];
__device__ __half g_wqkvt[3*Dd*Dd];
__device__ __half g_w1t[FFNf*Dd];
__device__ __half g_w2t[Dd*FFNf];
__device__ float  g_bqkv[3*Dd];

// ---------------- helpers -------------------------------------------------------
__device__ __forceinline__ uint32_t smem_u32(const void* p) {
    uint32_t a;
    asm("{ .reg .u64 t; cvta.to.shared.u64 t, %1; cvt.u32.u64 %0, t; }" : "=r"(a) : "l"(p));
    return a;
}
#define CP16(dst, src)  asm volatile("cp.async.ca.shared.global [%0], [%1], 16;" :: "r"(dst), "l"(src) : "memory")
#define CP_COMMIT()     asm volatile("cp.async.commit_group;" ::: "memory")
#define CP_WAIT1()      asm volatile("cp.async.wait_group 1;" ::: "memory")
#define LDSM4(r0,r1,r2,r3,a) \
    asm volatile("ldmatrix.sync.aligned.m8n8.x4.shared.b16 {%0,%1,%2,%3}, [%4];" \
        : "=r"(r0),"=r"(r1),"=r"(r2),"=r"(r3) : "r"(a))
#define LDSM4T(r0,r1,r2,r3,a) \
    asm volatile("ldmatrix.sync.aligned.m8n8.x4.trans.shared.b16 {%0,%1,%2,%3}, [%4];" \
        : "=r"(r0),"=r"(r1),"=r"(r2),"=r"(r3) : "r"(a))

__device__ __forceinline__ void mma16(float4& d,
                                      uint32_t a0, uint32_t a1, uint32_t a2, uint32_t a3,
                                      uint32_t b0, uint32_t b1) {
    asm volatile(
        "mma.sync.aligned.m16n8k16.row.col.f32.f16.f16.f32 "
        "{%0,%1,%2,%3}, {%4,%5,%6,%7}, {%8,%9}, {%0,%1,%2,%3};"
        : "+f"(d.x), "+f"(d.y), "+f"(d.z), "+f"(d.w)
        : "r"(a0), "r"(a1), "r"(a2), "r"(a3), "r"(b0), "r"(b1));
}

// ---------------- LayerNorm (fp32 + fp16 outputs) --------------------------------
__global__ __launch_bounds__(256) void ln_kernel(const float* __restrict__ x,
                                                 const float* __restrict__ gam,
                                                 const float* __restrict__ bet,
                                                 float* __restrict__ out32,
                                                 __half* __restrict__ out16)
{
    const int row = blockIdx.x;
    const int tid = threadIdx.x;
    const float2 v = ((const float2*)(x + (size_t)row * Dd))[tid];
    float s = v.x + v.y, ss = v.x * v.x + v.y * v.y;
    #pragma unroll
    for (int o = 16; o; o >>= 1) {
        s  += __shfl_xor_sync(~0u, s,  o);
        ss += __shfl_xor_sync(~0u, ss, o);
    }
    __shared__ float rs[8], rss[8];
    if ((tid & 31) == 0) { rs[tid >> 5] = s; rss[tid >> 5] = ss; }
    __syncthreads();
    float tot = 0.f, tot2 = 0.f;
    #pragma unroll
    for (int i = 0; i < 8; i++) { tot += rs[i]; tot2 += rss[i]; }
    const float mean = tot * (1.0f / Dd);
    const float var  = tot2 * (1.0f / Dd) - mean * mean;
    const float rstd = rsqrtf(var + 1e-5f);
    const float2 g2 = ((const float2*)gam)[tid];
    const float2 b2 = ((const float2*)bet)[tid];
    float2 o;
    o.x = (v.x - mean) * rstd * g2.x + b2.x;
    o.y = (v.y - mean) * rstd * g2.y + b2.y;
    ((float2*)(out32 + (size_t)row * Dd))[tid] = o;
    ((__half2*)(out16 + (size_t)row * Dd))[tid] = __floats2half2_rn(o.x, o.y);
}

// ---------------- weight transpose [K,N] -> fp16 [N,K] ---------------------------
__global__ __launch_bounds__(256) void transpose_kernel(const float* __restrict__ W,
                                                        __half* __restrict__ Wt,
                                                        int K, int N)
{
    __shared__ float t[32][33];
    const int n0 = blockIdx.x * 32, k0 = blockIdx.y * 32;
    const int tx = threadIdx.x, ty = threadIdx.y;
    #pragma unroll
    for (int i = 0; i < 32; i += 8) t[ty + i][tx] = W[(size_t)(k0 + ty + i) * N + n0 + tx];
    __syncthreads();
    #pragma unroll
    for (int i = 0; i < 32; i += 8)
        Wt[(size_t)(n0 + ty + i) * K + k0 + tx] = __float2half_rn(t[tx][ty + i]);
}

__global__ void pack_bias(const float* __restrict__ bq, const float* __restrict__ bk,
                          const float* __restrict__ bv, float* __restrict__ o)
{
    const int i = blockIdx.x * 256 + threadIdx.x;
    if (i < 512) o[i] = bq[i];
    else if (i < 1024) o[i] = bk[i - 512];
    else if (i < 1536) o[i] = bv[i - 1024];
}

// ---------------- fp16 warp-MMA GEMM, 2-stage cp.async pipeline ------------------
// MODE 0: write fp16 C16   MODE 1: qkv scatter fp16 (N=1536)   MODE 2: fp32 +res
template<int MODE>
__global__ __launch_bounds__(256, 2) void mma_gemm(const __half* __restrict__ A,
                                                   const __half* __restrict__ Bt,
                                                   const float* __restrict__ bias,
                                                   const float* __restrict__ res,
                                                   float* __restrict__ C,
                                                   __half* __restrict__ C16,
                                                   int M, int N, int K)
{
    __shared__ __align__(16) uint32_t sA[2][STAGE_WORDS];
    __shared__ __align__(16) uint32_t sB[2][STAGE_WORDS];

    const int tid  = threadIdx.x;
    const int m0   = blockIdx.y * 128;
    const int n0   = blockIdx.x * 128;
    const int w    = tid >> 5, lane = tid & 31;
    const int wm   = (w & 1) * 64;
    const int wn   = (w >> 1) * 32;
    const int r    = lane >> 2;
    const int c    = lane & 3;

    float4 acc[4][4];
    #pragma unroll
    for (int i = 0; i < 4; i++)
        #pragma unroll
        for (int j = 0; j < 4; j++) acc[i][j] = make_float4(0.f, 0.f, 0.f, 0.f);

    const uint32_t sAbase = smem_u32(sA);
    const uint32_t sBbase = smem_u32(sB);
    const int lrow = tid >> 1;
    const int lsel = tid & 1;
    const uint32_t ldst_off = (uint32_t)(lrow * PW + lsel * 8) * 4;
    const __half* asrc = A  + (size_t)(m0 + lrow) * K + lsel * 16;
    const __half* bsrc = Bt + (size_t)(n0 + lrow) * K + lsel * 16;

    const int T = K >> 5;

    #pragma unroll
    for (int p = 0; p < 2; p++) {
        const uint32_t ad = sAbase + p * STAGE_BYTES + ldst_off;
        const uint32_t bd = sBbase + p * STAGE_BYTES + ldst_off;
        const __half* as = asrc + p * 32;
        const __half* bs = bsrc + p * 32;
        CP16(ad, as); CP16(ad + 16, as + 8);
        CP16(bd, bs); CP16(bd + 16, bs + 8);
        CP_COMMIT();
    }

    for (int t = 0; t < T; t++) {
        CP_WAIT1();
        __syncthreads();
        const int buf = t & 1;
        const uint32_t* sAb = sA[buf];
        const uint32_t* sBb = sB[buf];

        #pragma unroll
        for (int kg = 0; kg < 2; kg++) {
            const int kwb = kg * 8 + c;
            uint32_t af[4][4];
            #pragma unroll
            for (int mt = 0; mt < 4; mt++) {
                const int mr = wm + mt * 16 + r;
                af[mt][0] = sAb[mr * PW + kwb];
                af[mt][1] = sAb[(mr + 8) * PW + kwb];
                af[mt][2] = sAb[mr * PW + kwb + 4];
                af[mt][3] = sAb[(mr + 8) * PW + kwb + 4];
            }
            uint32_t bf[4][2];
            #pragma unroll
            for (int nt = 0; nt < 4; nt++) {
                const int nr = wn + nt * 8 + r;
                bf[nt][0] = sBb[nr * PW + kwb];
                bf[nt][1] = sBb[nr * PW + kwb + 4];
            }
            #pragma unroll
            for (int mt = 0; mt < 4; mt++)
                #pragma unroll
                for (int nt = 0; nt < 4; nt++)
                    mma16(acc[mt][nt], af[mt][0], af[mt][1], af[mt][2], af[mt][3],
                          bf[nt][0], bf[nt][1]);
        }
        __syncthreads();

        if (t + 2 < T) {
            const uint32_t ad = sAbase + buf * STAGE_BYTES + ldst_off;
            const uint32_t bd = sBbase + buf * STAGE_BYTES + ldst_off;
            const __half* as = asrc + (t + 2) * 32;
            const __half* bs = bsrc + (t + 2) * 32;
            CP16(ad, as); CP16(ad + 16, as + 8);
            CP16(bd, bs); CP16(bd + 16, bs + 8);
        }
        CP_COMMIT();
    }

    #pragma unroll
    for (int mt = 0; mt < 4; mt++) {
        #pragma unroll
        for (int nt = 0; nt < 4; nt++) {
            const int m = m0 + wm + mt * 16 + r;
            const int n = n0 + wn + nt * 8 + c * 2;
            const float2 bv = *(const float2*)&bias[n];
            float2 lo, hi;
            lo.x = acc[mt][nt].x + bv.x;  lo.y = acc[mt][nt].y + bv.y;
            hi.x = acc[mt][nt].z + bv.x;  hi.y = acc[mt][nt].w + bv.y;
            if (MODE == 2) {
                const float2 r0 = *(const float2*)&res[(size_t)m * N + n];
                const float2 r1 = *(const float2*)&res[(size_t)(m + 8) * N + n];
                lo.x += r0.x; lo.y += r0.y;
                hi.x += r1.x; hi.y += r1.y;
            }
            if (MODE == 1) {
                const int which = n >> 9;
                const int nn = n & 511;
                const int hh = nn >> 6, d = nn & 63;
                const int b0i = m >> 11, s0 = m & (Ss - 1);
                const int b1i = (m + 8) >> 11, s1 = (m + 8) & (Ss - 1);
                __half* base = C16 + (size_t)which * ROWS * Dd;
                *(__half2*)&base[((((size_t)b0i * Hh + hh) * Ss) + s0) * DKk + d] =
                    __floats2half2_rn(lo.x, lo.y);
                *(__half2*)&base[((((size_t)b1i * Hh + hh) * Ss) + s1) * DKk + d] =
                    __floats2half2_rn(hi.x, hi.y);
            } else if (MODE == 0) {
                *(__half2*)&C16[(size_t)m * N + n]       = __floats2half2_rn(lo.x, lo.y);
                *(__half2*)&C16[(size_t)(m + 8) * N + n] = __floats2half2_rn(hi.x, hi.y);
            } else {
                *(float2*)&C[(size_t)m * N + n]       = lo;
                *(float2*)&C[(size_t)(m + 8) * N + n] = hi;
            }
        }
    }
}

// ---------------- MMA flash attention (banded, maskless) -------------------------
// grid (16 chunks, B*H); 8 warps, warp w = 16 queries. Key tiles of 64, all fully
// inside the window (clip points are multiples of 64) -> no masking.
__global__ __launch_bounds__(256, 2) void attn_mma(const __half* __restrict__ qh,
                                                   const __half* __restrict__ kh,
                                                   const __half* __restrict__ vh,
                                                   const float* __restrict__ hin,
                                                   float* __restrict__ out)
{
    __shared__ __align__(16) __half sK[2][64 * KVP];
    __shared__ __align__(16) __half sV[2][64 * KVP];

    const int bh  = blockIdx.y;
    const int cs  = blockIdx.x * 128;
    const int tid = threadIdx.x;
    const int w = tid >> 5, lane = tid & 31;
    const int r = lane >> 2;
    const int c = lane & 3;
    const size_t bhS = (size_t)bh * Ss;

    // Q fragments, pre-scaled by 1/8
    uint32_t qf[4][4];
    {
        const int q0 = cs + w * 16;
        const __half2 scl = __half2half2(__float2half(0.125f));
        #pragma unroll
        for (int ks = 0; ks < 4; ks++) {
            const __half* qp0 = qh + (bhS + q0 + r) * DKk + ks * 16 + c * 2;
            const __half* qp1 = qp0 + 8 * DKk;
            __half2 a0 = __hmul2(*(const __half2*)qp0, scl);
            __half2 a1 = __hmul2(*(const __half2*)qp1, scl);
            __half2 a2 = __hmul2(*(const __half2*)(qp0 + 8), scl);
            __half2 a3 = __hmul2(*(const __half2*)(qp1 + 8), scl);
            qf[ks][0] = *(uint32_t*)&a0; qf[ks][1] = *(uint32_t*)&a1;
            qf[ks][2] = *(uint32_t*)&a2; qf[ks][3] = *(uint32_t*)&a3;
        }
    }

    const int srow = tid >> 2;
    const int soff = (tid & 3) * 16;   // half offset within 64-half row (0,16,32,48)
    const uint32_t kdst0 = smem_u32(&sK[0][srow * KVP + soff]);
    const uint32_t vdst0 = smem_u32(&sV[0][srow * KVP + soff]);
    const int STG = 64 * KVP * 2;      // stage stride bytes

    int w0 = cs - 512; if (w0 < 0) w0 = 0;
    int w1 = cs + 256; if (w1 > Ss) w1 = Ss;
    const int T = (w1 - w0) >> 6;

    {   // prefetch
        const __half* ksrc = kh + (bhS + w0 + srow) * DKk + soff;
        const __half* vsrc = vh + (bhS + w0 + srow) * DKk + soff;
        CP16(kdst0, ksrc); CP16(kdst0 + 16, ksrc + 8);
        CP16(vdst0, vsrc); CP16(vdst0 + 16, vsrc + 8);
        CP_COMMIT();
        if (T > 1) {
            CP16(kdst0 + STG, ksrc + 64 * DKk); CP16(kdst0 + STG + 16, ksrc + 64 * DKk + 8);
            CP16(vdst0 + STG, vsrc + 64 * DKk); CP16(vdst0 + STG + 16, vsrc + 64 * DKk + 8);
        }
        CP_COMMIT();
    }

    float m0 = -1e30f, m1 = -1e30f, l0 = 0.f, l1 = 0.f;
    float4 accO[8];
    #pragma unroll
    for (int i = 0; i < 8; i++) accO[i] = make_float4(0.f, 0.f, 0.f, 0.f);

    // ldmatrix lane address components
    const int qk_row = (lane & 7) + ((lane >> 4) & 1) * 8;   // within 16-key group
    const int qk_col = ((lane >> 3) & 1) * 8;                // within 16-dim group
    const int pv_row = (lane & 7) + ((lane >> 3) & 1) * 8;   // within 16-key group
    const int pv_col = ((lane >> 4) & 1) * 8;                // within 16-dim group

    for (int t = 0; t < T; t++) {
        CP_WAIT1();
        __syncthreads();
        const int buf = t & 1;
        const uint32_t sKb = smem_u32(sK[buf]);
        const uint32_t sVb = smem_u32(sV[buf]);

        // ---- QK^T ----
        float4 s[8];
        #pragma unroll
        for (int i = 0; i < 8; i++) s[i] = make_float4(0.f, 0.f, 0.f, 0.f);
        #pragma unroll
        for (int ks = 0; ks < 4; ks++) {
            #pragma unroll
            for (int n2 = 0; n2 < 4; n2++) {
                uint32_t b0, b1, b2, b3;
                const uint32_t a = sKb +
                    (uint32_t)((n2 * 16 + qk_row) * KVP + ks * 16 + qk_col) * 2;
                LDSM4(b0, b1, b2, b3, a);
                mma16(s[2 * n2],     qf[ks][0], qf[ks][1], qf[ks][2], qf[ks][3], b0, b1);
                mma16(s[2 * n2 + 1], qf[ks][0], qf[ks][1], qf[ks][2], qf[ks][3], b2, b3);
            }
        }

        // ---- online softmax ----
        float mt0 = m0, mt1 = m1;
        #pragma unroll
        for (int i = 0; i < 8; i++) {
            mt0 = fmaxf(mt0, fmaxf(s[i].x, s[i].y));
            mt1 = fmaxf(mt1, fmaxf(s[i].z, s[i].w));
        }
        mt0 = fmaxf(mt0, __shfl_xor_sync(~0u, mt0, 1));
        mt0 = fmaxf(mt0, __shfl_xor_sync(~0u, mt0, 2));
        mt1 = fmaxf(mt1, __shfl_xor_sync(~0u, mt1, 1));
        mt1 = fmaxf(mt1, __shfl_xor_sync(~0u, mt1, 2));
        const float al0 = __expf(m0 - mt0);
        const float al1 = __expf(m1 - mt1);
        m0 = mt0; m1 = mt1;
        l0 *= al0; l1 *= al1;
        #pragma unroll
        for (int i = 0; i < 8; i++) {
            accO[i].x *= al0; accO[i].y *= al0;
            accO[i].z *= al1; accO[i].w *= al1;
        }
        float ps0 = 0.f, ps1 = 0.f;
        #pragma unroll
        for (int i = 0; i < 8; i++) {
            s[i].x = __expf(s[i].x - m0); s[i].y = __expf(s[i].y - m0);
            s[i].z = __expf(s[i].z - m1); s[i].w = __expf(s[i].w - m1);
            ps0 += s[i].x + s[i].y;
            ps1 += s[i].z + s[i].w;
        }
        ps0 += __shfl_xor_sync(~0u, ps0, 1); ps0 += __shfl_xor_sync(~0u, ps0, 2);
        ps1 += __shfl_xor_sync(~0u, ps1, 1); ps1 += __shfl_xor_sync(~0u, ps1, 2);
        l0 += ps0; l1 += ps1;

        // ---- P -> fp16 A-fragments ----
        uint32_t pf[4][4];
        #pragma unroll
        for (int ks = 0; ks < 4; ks++) {
            __half2 h;
            h = __floats2half2_rn(s[2 * ks].x,     s[2 * ks].y);     pf[ks][0] = *(uint32_t*)&h;
            h = __floats2half2_rn(s[2 * ks].z,     s[2 * ks].w);     pf[ks][1] = *(uint32_t*)&h;
            h = __floats2half2_rn(s[2 * ks + 1].x, s[2 * ks + 1].y); pf[ks][2] = *(uint32_t*)&h;
            h = __floats2half2_rn(s[2 * ks + 1].z, s[2 * ks + 1].w); pf[ks][3] = *(uint32_t*)&h;
        }

        // ---- P @ V ----
        #pragma unroll
        for (int ks = 0; ks < 4; ks++) {
            #pragma unroll
            for (int d2 = 0; d2 < 4; d2++) {
                uint32_t b0, b1, b2, b3;
                const uint32_t a = sVb +
                    (uint32_t)((ks * 16 + pv_row) * KVP + d2 * 16 + pv_col) * 2;
                LDSM4T(b0, b1, b2, b3, a);
                mma16(accO[2 * d2],     pf[ks][0], pf[ks][1], pf[ks][2], pf[ks][3], b0, b1);
                mma16(accO[2 * d2 + 1], pf[ks][0], pf[ks][1], pf[ks][2], pf[ks][3], b2, b3);
            }
        }

        __syncthreads();
        if (t + 2 < T) {
            const int j0 = w0 + (t + 2) * 64;
            const __half* ksrc = kh + (bhS + j0 + srow) * DKk + soff;
            const __half* vsrc = vh + (bhS + j0 + srow) * DKk + soff;
            const uint32_t kd = kdst0 + buf * STG;
            const uint32_t vd = vdst0 + buf * STG;
            CP16(kd, ksrc); CP16(kd + 16, ksrc + 8);
            CP16(vd, vsrc); CP16(vd + 16, vsrc + 8);
        }
        CP_COMMIT();
    }

    // ---- epilogue: O/l + residual h ----
    const float inv0 = 1.0f / l0;
    const float inv1 = 1.0f / l1;
    const int b = bh >> 3, head = bh & 7;
    const int q0 = cs + w * 16;
    const size_t base0 = ((size_t)b * Ss + q0 + r) * Dd + head * DKk;
    const size_t base1 = base0 + 8 * Dd;
    #pragma unroll
    for (int dn = 0; dn < 8; dn++) {
        const int d = dn * 8 + c * 2;
        const float2 h0 = *(const float2*)&hin[base0 + d];
        const float2 h1 = *(const float2*)&hin[base1 + d];
        float2 o0, o1;
        o0.x = accO[dn].x * inv0 + h0.x;  o0.y = accO[dn].y * inv0 + h0.y;
        o1.x = accO[dn].z * inv1 + h1.x;  o1.y = accO[dn].w * inv1 + h1.y;
        *(float2*)&out[base0 + d] = o0;
        *(float2*)&out[base1 + d] = o1;
    }
}

// ---------------- launch ----------------------------------------------------------
extern "C" void kernel_launch(void* const* d_in, const int* in_sizes, int n_in,
                              void* d_out, int out_size)
{
    const float* x       = (const float*)d_in[0];
    const float* ln_in_g = (const float*)d_in[2];
    const float* ln_in_b = (const float*)d_in[3];
    const float* wq = (const float*)d_in[4];  const float* bq = (const float*)d_in[5];
    const float* wk = (const float*)d_in[6];  const float* bk = (const float*)d_in[7];
    const float* wv = (const float*)d_in[8];  const float* bv = (const float*)d_in[9];
    const float* ln1_g = (const float*)d_in[10]; const float* ln1_b = (const float*)d_in[11];
    const float* w1 = (const float*)d_in[12]; const float* b1 = (const float*)d_in[13];
    const float* w2 = (const float*)d_in[14]; const float* b2 = (const float*)d_in[15];
    const float* ln2_g = (const float*)d_in[16]; const float* ln2_b = (const float*)d_in[17];
    float* out = (float*)d_out;

    float *ph, *pattn, *plns, *pr, *pbqkv;
    __half *ph16, *pqkv16, *po16, *pf16, *pwqkvt, *pw1t, *pw2t;
    cudaGetSymbolAddress((void**)&ph,     g_h);
    cudaGetSymbolAddress((void**)&ph16,   g_h16);
    cudaGetSymbolAddress((void**)&pqkv16, g_qkv16);
    cudaGetSymbolAddress((void**)&pattn,  g_attn);
    cudaGetSymbolAddress((void**)&plns,   g_lnscratch);
    cudaGetSymbolAddress((void**)&po16,   g_o16);
    cudaGetSymbolAddress((void**)&pf16,   g_f16);
    cudaGetSymbolAddress((void**)&pr,     g_r);
    cudaGetSymbolAddress((void**)&pwqkvt, g_wqkvt);
    cudaGetSymbolAddress((void**)&pw1t,   g_w1t);
    cudaGetSymbolAddress((void**)&pw2t,   g_w2t);
    cudaGetSymbolAddress((void**)&pbqkv,  g_bqkv);

    dim3 tb(32, 8);
    transpose_kernel<<<dim3(Dd / 32, Dd / 32), tb>>>(wq, pwqkvt, Dd, Dd);
    transpose_kernel<<<dim3(Dd / 32, Dd / 32), tb>>>(wk, pwqkvt + Dd * Dd, Dd, Dd);
    transpose_kernel<<<dim3(Dd / 32, Dd / 32), tb>>>(wv, pwqkvt + 2 * Dd * Dd, Dd, Dd);
    transpose_kernel<<<dim3(FFNf / 32, Dd / 32), tb>>>(w1, pw1t, Dd, FFNf);
    transpose_kernel<<<dim3(Dd / 32, FFNf / 32), tb>>>(w2, pw2t, FFNf, Dd);
    pack_bias<<<6, 256>>>(bq, bk, bv, pbqkv);

    // 1. h = LN(x)
    ln_kernel<<<ROWS, 256>>>(x, ln_in_g, ln_in_b, ph, ph16);

    // 2. fused QKV (fp16 out)
    mma_gemm<1><<<dim3(12, 64), 256>>>(ph16, pwqkvt, pbqkv, nullptr, nullptr, pqkv16,
                                       ROWS, 3 * Dd, Dd);

    // 3. MMA flash attention + residual h
    attn_mma<<<dim3(Ss / 128, Bb * Hh), 256>>>(pqkv16,
                                               pqkv16 + (size_t)ROWS * Dd,
                                               pqkv16 + 2 * (size_t)ROWS * Dd,
                                               ph, pattn);

    // 4. LN1 -> fp16
    ln_kernel<<<ROWS, 256>>>(pattn, ln1_g, ln1_b, plns, po16);

    // 5. FFN
    mma_gemm<0><<<dim3(FFNf / 128, 64), 256>>>(po16, pw1t, b1, nullptr, nullptr, pf16,
                                               ROWS, FFNf, Dd);
    mma_gemm<2><<<dim3(Dd / 128, 64), 256>>>(pf16, pw2t, b2, pattn, pr, nullptr,
                                             ROWS, Dd, FFNf);

    // 6. out = LN2
    ln_kernel<<<ROWS, 256>>>(pr, ln2_g, ln2_b, out, ph16);
}

// round 7
// speedup vs baseline: 5.4991x; 1.1495x over previous
#include <cuda_runtime.h>
#include <cuda_fp16.h>
#include <cstdint>

#define Bb   4
#define Ss   2048
#define Dd   512
#define Hh   8
#define DKk  64
#define FFNf 2048
#define ROWS (Bb*Ss)   // 8192
#define GP   80                 // gemm smem pitch in BYTES (40 halves; 16B-aligned, conflict-free)
#define SBYTES (128*GP)         // bytes per stage per tensor
#define KVP  72                 // attn K/V smem pitch in halves (144B rows)

// ---------------- scratch -------------------------------------------------------
__device__ float  g_h[ROWS*Dd];
__device__ __half g_h16[ROWS*Dd];
__device__ __half g_qkv16[3*ROWS*Dd];
__device__ float  g_attn[ROWS*Dd];
__device__ __half g_o16[ROWS*Dd];
__device__ __half g_f16[ROWS*FFNf];
__device__ float  g_r[ROWS*Dd];
__device__ __half g_wqkvt[3*Dd*Dd];
__device__ __half g_w1t[FFNf*Dd];
__device__ __half g_w2t[Dd*FFNf];
__device__ float  g_bqkv[3*Dd];

// ---------------- helpers -------------------------------------------------------
__device__ __forceinline__ uint32_t smem_u32(const void* p) {
    uint32_t a;
    asm("{ .reg .u64 t; cvta.to.shared.u64 t, %1; cvt.u32.u64 %0, t; }" : "=r"(a) : "l"(p));
    return a;
}
#define CP16(dst, src)  asm volatile("cp.async.ca.shared.global [%0], [%1], 16;" :: "r"(dst), "l"(src) : "memory")
#define CP_COMMIT()     asm volatile("cp.async.commit_group;" ::: "memory")
#define CP_WAIT1()      asm volatile("cp.async.wait_group 1;" ::: "memory")
#define LDSM4(r0,r1,r2,r3,a) \
    asm volatile("ldmatrix.sync.aligned.m8n8.x4.shared.b16 {%0,%1,%2,%3}, [%4];" \
        : "=r"(r0),"=r"(r1),"=r"(r2),"=r"(r3) : "r"(a))
#define LDSM4T(r0,r1,r2,r3,a) \
    asm volatile("ldmatrix.sync.aligned.m8n8.x4.trans.shared.b16 {%0,%1,%2,%3}, [%4];" \
        : "=r"(r0),"=r"(r1),"=r"(r2),"=r"(r3) : "r"(a))

__device__ __forceinline__ void mma16(float4& d,
                                      uint32_t a0, uint32_t a1, uint32_t a2, uint32_t a3,
                                      uint32_t b0, uint32_t b1) {
    asm volatile(
        "mma.sync.aligned.m16n8k16.row.col.f32.f16.f16.f32 "
        "{%0,%1,%2,%3}, {%4,%5,%6,%7}, {%8,%9}, {%0,%1,%2,%3};"
        : "+f"(d.x), "+f"(d.y), "+f"(d.z), "+f"(d.w)
        : "r"(a0), "r"(a1), "r"(a2), "r"(a3), "r"(b0), "r"(b1));
}

// ---------------- LayerNorm -------------------------------------------------------
__global__ __launch_bounds__(256) void ln_kernel(const float* __restrict__ x,
                                                 const float* __restrict__ gam,
                                                 const float* __restrict__ bet,
                                                 float* __restrict__ out32,
                                                 __half* __restrict__ out16)
{
    const int row = blockIdx.x;
    const int tid = threadIdx.x;
    const float2 v = ((const float2*)(x + (size_t)row * Dd))[tid];
    float s = v.x + v.y, ss = v.x * v.x + v.y * v.y;
    #pragma unroll
    for (int o = 16; o; o >>= 1) {
        s  += __shfl_xor_sync(~0u, s,  o);
        ss += __shfl_xor_sync(~0u, ss, o);
    }
    __shared__ float rs[8], rss[8];
    if ((tid & 31) == 0) { rs[tid >> 5] = s; rss[tid >> 5] = ss; }
    __syncthreads();
    float tot = 0.f, tot2 = 0.f;
    #pragma unroll
    for (int i = 0; i < 8; i++) { tot += rs[i]; tot2 += rss[i]; }
    const float mean = tot * (1.0f / Dd);
    const float var  = tot2 * (1.0f / Dd) - mean * mean;
    const float rstd = rsqrtf(var + 1e-5f);
    const float2 g2 = ((const float2*)gam)[tid];
    const float2 b2 = ((const float2*)bet)[tid];
    float2 o;
    o.x = (v.x - mean) * rstd * g2.x + b2.x;
    o.y = (v.y - mean) * rstd * g2.y + b2.y;
    if (out32) ((float2*)(out32 + (size_t)row * Dd))[tid] = o;
    if (out16) ((__half2*)(out16 + (size_t)row * Dd))[tid] = __floats2half2_rn(o.x, o.y);
}

// ---------------- merged prep: 5 weight transposes + bias pack --------------------
__global__ __launch_bounds__(256) void prep_kernel(
    const float* __restrict__ wq, const float* __restrict__ wk, const float* __restrict__ wv,
    const float* __restrict__ w1, const float* __restrict__ w2,
    const float* __restrict__ bq, const float* __restrict__ bk, const float* __restrict__ bv,
    __half* __restrict__ wqkvt, __half* __restrict__ w1t, __half* __restrict__ w2t,
    float* __restrict__ bqkv)
{
    const int b = blockIdx.x;
    const int tid = threadIdx.x;
    if (b >= 2816) {
        const int i = (b - 2816) * 256 + tid;
        if (i < 512) bqkv[i] = bq[i];
        else if (i < 1024) bqkv[i] = bk[i - 512];
        else if (i < 1536) bqkv[i] = bv[i - 1024];
        return;
    }
    const float* W; __half* Wt; int K, N, n0, k0;
    if (b < 768) {
        const int which = b >> 8, t = b & 255;
        W = which == 0 ? wq : (which == 1 ? wk : wv);
        Wt = wqkvt + (size_t)which * Dd * Dd;
        K = Dd; N = Dd;
        n0 = (t & 15) * 32; k0 = (t >> 4) * 32;
    } else if (b < 1792) {
        const int t = b - 768;
        W = w1; Wt = w1t; K = Dd; N = FFNf;
        n0 = (t & 63) * 32; k0 = (t >> 6) * 32;
    } else {
        const int t = b - 1792;
        W = w2; Wt = w2t; K = FFNf; N = Dd;
        n0 = (t & 15) * 32; k0 = (t >> 4) * 32;
    }
    __shared__ float t[32][33];
    const int tx = tid & 31, ty = tid >> 5;
    #pragma unroll
    for (int i = 0; i < 32; i += 8) t[ty + i][tx] = W[(size_t)(k0 + ty + i) * N + n0 + tx];
    __syncthreads();
    #pragma unroll
    for (int i = 0; i < 32; i += 8)
        Wt[(size_t)(n0 + ty + i) * K + k0 + tx] = __float2half_rn(t[tx][ty + i]);
}

// ---------------- fp16 warp-MMA GEMM (ldmatrix mainloop, 80B pitch) ---------------
// MODE 0: write fp16 C16   MODE 1: qkv scatter fp16 (N=1536)   MODE 2: fp32 +res
template<int MODE>
__global__ __launch_bounds__(256, 2) void mma_gemm(const __half* __restrict__ A,
                                                   const __half* __restrict__ Bt,
                                                   const float* __restrict__ bias,
                                                   const float* __restrict__ res,
                                                   float* __restrict__ C,
                                                   __half* __restrict__ C16,
                                                   int M, int N, int K)
{
    __shared__ __align__(16) char sA[2 * SBYTES];   // 10KB/stage
    __shared__ __align__(16) char sB[2 * SBYTES];

    const int tid  = threadIdx.x;
    const int m0   = blockIdx.y * 128;
    const int n0   = blockIdx.x * 128;
    const int w    = tid >> 5, lane = tid & 31;
    const int wm   = (w & 1) * 64;
    const int wn   = (w >> 1) * 32;
    const int r    = lane >> 2;
    const int c    = lane & 3;
    const int g    = lane >> 3, lr = lane & 7;

    float4 acc[4][4];
    #pragma unroll
    for (int i = 0; i < 4; i++)
        #pragma unroll
        for (int j = 0; j < 4; j++) acc[i][j] = make_float4(0.f, 0.f, 0.f, 0.f);

    const uint32_t sAbase = smem_u32(sA);
    const uint32_t sBbase = smem_u32(sB);

    // cp.async staging: thread -> row tid>>1, halves (tid&1)*16..+15 (32B each)
    const int lrow = tid >> 1;
    const int lsel = tid & 1;
    const uint32_t ldst_off = (uint32_t)(lrow * GP + lsel * 32);   // 16B-aligned
    const __half* asrc = A  + (size_t)(m0 + lrow) * K + lsel * 16;
    const __half* bsrc = Bt + (size_t)(n0 + lrow) * K + lsel * 16;

    // ldmatrix lane offsets (bytes from stage base)
    const uint32_t aoff = (uint32_t)((wm + (g & 1) * 8 + lr) * GP + (g >> 1) * 16);
    const uint32_t boff = (uint32_t)((wn + ((g >> 1) & 1) * 8 + lr) * GP + (g & 1) * 16);

    const int T = K >> 5;

    #pragma unroll
    for (int p = 0; p < 2; p++) {
        const uint32_t ad = sAbase + p * SBYTES + ldst_off;
        const uint32_t bd = sBbase + p * SBYTES + ldst_off;
        const __half* as = asrc + p * 32;
        const __half* bs = bsrc + p * 32;
        CP16(ad, as); CP16(ad + 16, as + 8);
        CP16(bd, bs); CP16(bd + 16, bs + 8);
        CP_COMMIT();
    }

    for (int t = 0; t < T; t++) {
        CP_WAIT1();
        __syncthreads();
        const int buf = t & 1;
        const uint32_t sAb = sAbase + buf * SBYTES;
        const uint32_t sBb = sBbase + buf * SBYTES;

        #pragma unroll
        for (int kg = 0; kg < 2; kg++) {
            uint32_t af[4][4];
            #pragma unroll
            for (int mt = 0; mt < 4; mt++)
                LDSM4(af[mt][0], af[mt][1], af[mt][2], af[mt][3],
                      sAb + aoff + (uint32_t)(mt * 16 * GP + kg * 32));
            uint32_t bf[2][4];
            #pragma unroll
            for (int nt2 = 0; nt2 < 2; nt2++)
                LDSM4(bf[nt2][0], bf[nt2][1], bf[nt2][2], bf[nt2][3],
                      sBb + boff + (uint32_t)(nt2 * 16 * GP + kg * 32));
            #pragma unroll
            for (int mt = 0; mt < 4; mt++) {
                #pragma unroll
                for (int nt2 = 0; nt2 < 2; nt2++) {
                    mma16(acc[mt][nt2 * 2],     af[mt][0], af[mt][1], af[mt][2], af[mt][3],
                          bf[nt2][0], bf[nt2][1]);
                    mma16(acc[mt][nt2 * 2 + 1], af[mt][0], af[mt][1], af[mt][2], af[mt][3],
                          bf[nt2][2], bf[nt2][3]);
                }
            }
        }
        __syncthreads();

        if (t + 2 < T) {
            const uint32_t ad = sAbase + buf * SBYTES + ldst_off;
            const uint32_t bd = sBbase + buf * SBYTES + ldst_off;
            const __half* as = asrc + (t + 2) * 32;
            const __half* bs = bsrc + (t + 2) * 32;
            CP16(ad, as); CP16(ad + 16, as + 8);
            CP16(bd, bs); CP16(bd + 16, bs + 8);
        }
        CP_COMMIT();
    }

    #pragma unroll
    for (int mt = 0; mt < 4; mt++) {
        #pragma unroll
        for (int nt = 0; nt < 4; nt++) {
            const int m = m0 + wm + mt * 16 + r;
            const int n = n0 + wn + nt * 8 + c * 2;
            const float2 bv = *(const float2*)&bias[n];
            float2 lo, hi;
            lo.x = acc[mt][nt].x + bv.x;  lo.y = acc[mt][nt].y + bv.y;
            hi.x = acc[mt][nt].z + bv.x;  hi.y = acc[mt][nt].w + bv.y;
            if (MODE == 2) {
                const float2 r0 = *(const float2*)&res[(size_t)m * N + n];
                const float2 r1 = *(const float2*)&res[(size_t)(m + 8) * N + n];
                lo.x += r0.x; lo.y += r0.y;
                hi.x += r1.x; hi.y += r1.y;
            }
            if (MODE == 1) {
                const int which = n >> 9;
                const int nn = n & 511;
                const int hh = nn >> 6, d = nn & 63;
                const int b0i = m >> 11, s0 = m & (Ss - 1);
                const int b1i = (m + 8) >> 11, s1 = (m + 8) & (Ss - 1);
                __half* base = C16 + (size_t)which * ROWS * Dd;
                *(__half2*)&base[((((size_t)b0i * Hh + hh) * Ss) + s0) * DKk + d] =
                    __floats2half2_rn(lo.x, lo.y);
                *(__half2*)&base[((((size_t)b1i * Hh + hh) * Ss) + s1) * DKk + d] =
                    __floats2half2_rn(hi.x, hi.y);
            } else if (MODE == 0) {
                *(__half2*)&C16[(size_t)m * N + n]       = __floats2half2_rn(lo.x, lo.y);
                *(__half2*)&C16[(size_t)(m + 8) * N + n] = __floats2half2_rn(hi.x, hi.y);
            } else {
                *(float2*)&C[(size_t)m * N + n]       = lo;
                *(float2*)&C[(size_t)(m + 8) * N + n] = hi;
            }
        }
    }
}

// ---------------- MMA flash attention (banded, maskless) --------------------------
__global__ __launch_bounds__(256, 2) void attn_mma(const __half* __restrict__ qh,
                                                   const __half* __restrict__ kh,
                                                   const __half* __restrict__ vh,
                                                   const float* __restrict__ hin,
                                                   float* __restrict__ out)
{
    __shared__ __align__(16) __half sK[2][64 * KVP];
    __shared__ __align__(16) __half sV[2][64 * KVP];

    const int bh  = blockIdx.y;
    const int cs  = blockIdx.x * 128;
    const int tid = threadIdx.x;
    const int w = tid >> 5, lane = tid & 31;
    const int r = lane >> 2;
    const int c = lane & 3;
    const size_t bhS = (size_t)bh * Ss;

    uint32_t qf[4][4];
    {
        const int q0 = cs + w * 16;
        const __half2 scl = __half2half2(__float2half(0.125f));
        #pragma unroll
        for (int ks = 0; ks < 4; ks++) {
            const __half* qp0 = qh + (bhS + q0 + r) * DKk + ks * 16 + c * 2;
            const __half* qp1 = qp0 + 8 * DKk;
            __half2 a0 = __hmul2(*(const __half2*)qp0, scl);
            __half2 a1 = __hmul2(*(const __half2*)qp1, scl);
            __half2 a2 = __hmul2(*(const __half2*)(qp0 + 8), scl);
            __half2 a3 = __hmul2(*(const __half2*)(qp1 + 8), scl);
            qf[ks][0] = *(uint32_t*)&a0; qf[ks][1] = *(uint32_t*)&a1;
            qf[ks][2] = *(uint32_t*)&a2; qf[ks][3] = *(uint32_t*)&a3;
        }
    }

    const int srow = tid >> 2;
    const int soff = (tid & 3) * 16;
    const uint32_t kdst0 = smem_u32(&sK[0][srow * KVP + soff]);
    const uint32_t vdst0 = smem_u32(&sV[0][srow * KVP + soff]);
    const int STG = 64 * KVP * 2;

    int w0 = cs - 512; if (w0 < 0) w0 = 0;
    int w1 = cs + 256; if (w1 > Ss) w1 = Ss;
    const int T = (w1 - w0) >> 6;

    {
        const __half* ksrc = kh + (bhS + w0 + srow) * DKk + soff;
        const __half* vsrc = vh + (bhS + w0 + srow) * DKk + soff;
        CP16(kdst0, ksrc); CP16(kdst0 + 16, ksrc + 8);
        CP16(vdst0, vsrc); CP16(vdst0 + 16, vsrc + 8);
        CP_COMMIT();
        if (T > 1) {
            CP16(kdst0 + STG, ksrc + 64 * DKk); CP16(kdst0 + STG + 16, ksrc + 64 * DKk + 8);
            CP16(vdst0 + STG, vsrc + 64 * DKk); CP16(vdst0 + STG + 16, vsrc + 64 * DKk + 8);
        }
        CP_COMMIT();
    }

    float m0 = -1e30f, m1 = -1e30f, l0 = 0.f, l1 = 0.f;
    float4 accO[8];
    #pragma unroll
    for (int i = 0; i < 8; i++) accO[i] = make_float4(0.f, 0.f, 0.f, 0.f);

    const int qk_row = (lane & 7) + ((lane >> 4) & 1) * 8;
    const int qk_col = ((lane >> 3) & 1) * 8;
    const int pv_row = (lane & 7) + ((lane >> 3) & 1) * 8;
    const int pv_col = ((lane >> 4) & 1) * 8;

    for (int t = 0; t < T; t++) {
        CP_WAIT1();
        __syncthreads();
        const int buf = t & 1;
        const uint32_t sKb = smem_u32(sK[buf]);
        const uint32_t sVb = smem_u32(sV[buf]);

        float4 s[8];
        #pragma unroll
        for (int i = 0; i < 8; i++) s[i] = make_float4(0.f, 0.f, 0.f, 0.f);
        #pragma unroll
        for (int ks = 0; ks < 4; ks++) {
            #pragma unroll
            for (int n2 = 0; n2 < 4; n2++) {
                uint32_t b0, b1, b2, b3;
                const uint32_t a = sKb +
                    (uint32_t)((n2 * 16 + qk_row) * KVP + ks * 16 + qk_col) * 2;
                LDSM4(b0, b1, b2, b3, a);
                mma16(s[2 * n2],     qf[ks][0], qf[ks][1], qf[ks][2], qf[ks][3], b0, b1);
                mma16(s[2 * n2 + 1], qf[ks][0], qf[ks][1], qf[ks][2], qf[ks][3], b2, b3);
            }
        }

        float mt0 = m0, mt1 = m1;
        #pragma unroll
        for (int i = 0; i < 8; i++) {
            mt0 = fmaxf(mt0, fmaxf(s[i].x, s[i].y));
            mt1 = fmaxf(mt1, fmaxf(s[i].z, s[i].w));
        }
        mt0 = fmaxf(mt0, __shfl_xor_sync(~0u, mt0, 1));
        mt0 = fmaxf(mt0, __shfl_xor_sync(~0u, mt0, 2));
        mt1 = fmaxf(mt1, __shfl_xor_sync(~0u, mt1, 1));
        mt1 = fmaxf(mt1, __shfl_xor_sync(~0u, mt1, 2));
        const float al0 = __expf(m0 - mt0);
        const float al1 = __expf(m1 - mt1);
        m0 = mt0; m1 = mt1;
        l0 *= al0; l1 *= al1;
        #pragma unroll
        for (int i = 0; i < 8; i++) {
            accO[i].x *= al0; accO[i].y *= al0;
            accO[i].z *= al1; accO[i].w *= al1;
        }
        float ps0 = 0.f, ps1 = 0.f;
        #pragma unroll
        for (int i = 0; i < 8; i++) {
            s[i].x = __expf(s[i].x - m0); s[i].y = __expf(s[i].y - m0);
            s[i].z = __expf(s[i].z - m1); s[i].w = __expf(s[i].w - m1);
            ps0 += s[i].x + s[i].y;
            ps1 += s[i].z + s[i].w;
        }
        ps0 += __shfl_xor_sync(~0u, ps0, 1); ps0 += __shfl_xor_sync(~0u, ps0, 2);
        ps1 += __shfl_xor_sync(~0u, ps1, 1); ps1 += __shfl_xor_sync(~0u, ps1, 2);
        l0 += ps0; l1 += ps1;

        uint32_t pf[4][4];
        #pragma unroll
        for (int ks = 0; ks < 4; ks++) {
            __half2 h;
            h = __floats2half2_rn(s[2 * ks].x,     s[2 * ks].y);     pf[ks][0] = *(uint32_t*)&h;
            h = __floats2half2_rn(s[2 * ks].z,     s[2 * ks].w);     pf[ks][1] = *(uint32_t*)&h;
            h = __floats2half2_rn(s[2 * ks + 1].x, s[2 * ks + 1].y); pf[ks][2] = *(uint32_t*)&h;
            h = __floats2half2_rn(s[2 * ks + 1].z, s[2 * ks + 1].w); pf[ks][3] = *(uint32_t*)&h;
        }

        #pragma unroll
        for (int ks = 0; ks < 4; ks++) {
            #pragma unroll
            for (int d2 = 0; d2 < 4; d2++) {
                uint32_t b0, b1, b2, b3;
                const uint32_t a = sVb +
                    (uint32_t)((ks * 16 + pv_row) * KVP + d2 * 16 + pv_col) * 2;
                LDSM4T(b0, b1, b2, b3, a);
                mma16(accO[2 * d2],     pf[ks][0], pf[ks][1], pf[ks][2], pf[ks][3], b0, b1);
                mma16(accO[2 * d2 + 1], pf[ks][0], pf[ks][1], pf[ks][2], pf[ks][3], b2, b3);
            }
        }

        __syncthreads();
        if (t + 2 < T) {
            const int j0 = w0 + (t + 2) * 64;
            const __half* ksrc = kh + (bhS + j0 + srow) * DKk + soff;
            const __half* vsrc = vh + (bhS + j0 + srow) * DKk + soff;
            const uint32_t kd = kdst0 + buf * STG;
            const uint32_t vd = vdst0 + buf * STG;
            CP16(kd, ksrc); CP16(kd + 16, ksrc + 8);
            CP16(vd, vsrc); CP16(vd + 16, vsrc + 8);
        }
        CP_COMMIT();
    }

    const float inv0 = 1.0f / l0;
    const float inv1 = 1.0f / l1;
    const int b = bh >> 3, head = bh & 7;
    const int q0 = cs + w * 16;
    const size_t base0 = ((size_t)b * Ss + q0 + r) * Dd + head * DKk;
    const size_t base1 = base0 + 8 * Dd;
    #pragma unroll
    for (int dn = 0; dn < 8; dn++) {
        const int d = dn * 8 + c * 2;
        const float2 h0 = *(const float2*)&hin[base0 + d];
        const float2 h1 = *(const float2*)&hin[base1 + d];
        float2 o0, o1;
        o0.x = accO[dn].x * inv0 + h0.x;  o0.y = accO[dn].y * inv0 + h0.y;
        o1.x = accO[dn].z * inv1 + h1.x;  o1.y = accO[dn].w * inv1 + h1.y;
        *(float2*)&out[base0 + d] = o0;
        *(float2*)&out[base1 + d] = o1;
    }
}

// ---------------- launch ------------------------------------------------------------
extern "C" void kernel_launch(void* const* d_in, const int* in_sizes, int n_in,
                              void* d_out, int out_size)
{
    const float* x       = (const float*)d_in[0];
    const float* ln_in_g = (const float*)d_in[2];
    const float* ln_in_b = (const float*)d_in[3];
    const float* wq = (const float*)d_in[4];  const float* bq = (const float*)d_in[5];
    const float* wk = (const float*)d_in[6];  const float* bk = (const float*)d_in[7];
    const float* wv = (const float*)d_in[8];  const float* bv = (const float*)d_in[9];
    const float* ln1_g = (const float*)d_in[10]; const float* ln1_b = (const float*)d_in[11];
    const float* w1 = (const float*)d_in[12]; const float* b1 = (const float*)d_in[13];
    const float* w2 = (const float*)d_in[14]; const float* b2 = (const float*)d_in[15];
    const float* ln2_g = (const float*)d_in[16]; const float* ln2_b = (const float*)d_in[17];
    float* out = (float*)d_out;

    float *ph, *pattn, *pr, *pbqkv;
    __half *ph16, *pqkv16, *po16, *pf16, *pwqkvt, *pw1t, *pw2t;
    cudaGetSymbolAddress((void**)&ph,     g_h);
    cudaGetSymbolAddress((void**)&ph16,   g_h16);
    cudaGetSymbolAddress((void**)&pqkv16, g_qkv16);
    cudaGetSymbolAddress((void**)&pattn,  g_attn);
    cudaGetSymbolAddress((void**)&po16,   g_o16);
    cudaGetSymbolAddress((void**)&pf16,   g_f16);
    cudaGetSymbolAddress((void**)&pr,     g_r);
    cudaGetSymbolAddress((void**)&pwqkvt, g_wqkvt);
    cudaGetSymbolAddress((void**)&pw1t,   g_w1t);
    cudaGetSymbolAddress((void**)&pw2t,   g_w2t);
    cudaGetSymbolAddress((void**)&pbqkv,  g_bqkv);

    // 0. merged prep
    prep_kernel<<<2822, 256>>>(wq, wk, wv, w1, w2, bq, bk, bv,
                               pwqkvt, pw1t, pw2t, pbqkv);

    // 1. h = LN(x)
    ln_kernel<<<ROWS, 256>>>(x, ln_in_g, ln_in_b, ph, ph16);

    // 2. fused QKV (fp16 out)
    mma_gemm<1><<<dim3(12, 64), 256>>>(ph16, pwqkvt, pbqkv, nullptr, nullptr, pqkv16,
                                       ROWS, 3 * Dd, Dd);

    // 3. MMA flash attention + residual h
    attn_mma<<<dim3(Ss / 128, Bb * Hh), 256>>>(pqkv16,
                                               pqkv16 + (size_t)ROWS * Dd,
                                               pqkv16 + 2 * (size_t)ROWS * Dd,
                                               ph, pattn);

    // 4. LN1 -> fp16 only
    ln_kernel<<<ROWS, 256>>>(pattn, ln1_g, ln1_b, nullptr, po16);

    // 5. FFN
    mma_gemm<0><<<dim3(FFNf / 128, 64), 256>>>(po16, pw1t, b1, nullptr, nullptr, pf16,
                                               ROWS, FFNf, Dd);
    mma_gemm<2><<<dim3(Dd / 128, 64), 256>>>(pf16, pw2t, b2, pattn, pr, nullptr,
                                             ROWS, Dd, FFNf);

    // 6. out = LN2 (fp32 only)
    ln_kernel<<<ROWS, 256>>>(pr, ln2_g, ln2_b, out, nullptr);
}

// round 8
// speedup vs baseline: 5.6412x; 1.0258x over previous
#include <cuda_runtime.h>
#include <cuda_fp16.h>
#include <cstdint>

#define Bb   4
#define Ss   2048
#define Dd   512
#define Hh   8
#define DKk  64
#define FFNf 2048
#define ROWS (Bb*Ss)   // 8192
#define GP   80                  // gemm smem pitch bytes (16B-aligned, ldmatrix conflict-free)
#define SBYTES (128*GP)          // 10240 bytes per stage per tensor
#define GEMM_SMEM (6*SBYTES)     // 3 stages x {A,B}
#define KVP  72                  // attn K/V pitch in halves (144B rows)
#define KSTG (64*KVP*2)          // 9216 bytes per stage per tensor
#define ATTN_SMEM (6*KSTG)       // 3 stages x {K,V}

// ---------------- scratch -------------------------------------------------------
__device__ float  g_h[ROWS*Dd];
__device__ __half g_h16[ROWS*Dd];
__device__ __half g_qkv16[3*ROWS*Dd];
__device__ float  g_attn[ROWS*Dd];
__device__ __half g_o16[ROWS*Dd];
__device__ __half g_f16[ROWS*FFNf];
__device__ float  g_r[ROWS*Dd];
__device__ __half g_wqkvt[3*Dd*Dd];
__device__ __half g_w1t[FFNf*Dd];
__device__ __half g_w2t[Dd*FFNf];
__device__ float  g_bqkv[3*Dd];

// ---------------- helpers -------------------------------------------------------
__device__ __forceinline__ uint32_t smem_u32(const void* p) {
    uint32_t a;
    asm("{ .reg .u64 t; cvta.to.shared.u64 t, %1; cvt.u32.u64 %0, t; }" : "=r"(a) : "l"(p));
    return a;
}
#define CP16(dst, src)  asm volatile("cp.async.ca.shared.global [%0], [%1], 16;" :: "r"(dst), "l"(src) : "memory")
#define CP_COMMIT()     asm volatile("cp.async.commit_group;" ::: "memory")
#define CP_WAIT1()      asm volatile("cp.async.wait_group 1;" ::: "memory")
#define LDSM4(r0,r1,r2,r3,a) \
    asm volatile("ldmatrix.sync.aligned.m8n8.x4.shared.b16 {%0,%1,%2,%3}, [%4];" \
        : "=r"(r0),"=r"(r1),"=r"(r2),"=r"(r3) : "r"(a))
#define LDSM4T(r0,r1,r2,r3,a) \
    asm volatile("ldmatrix.sync.aligned.m8n8.x4.trans.shared.b16 {%0,%1,%2,%3}, [%4];" \
        : "=r"(r0),"=r"(r1),"=r"(r2),"=r"(r3) : "r"(a))

__device__ __forceinline__ void mma16(float4& d,
                                      uint32_t a0, uint32_t a1, uint32_t a2, uint32_t a3,
                                      uint32_t b0, uint32_t b1) {
    asm volatile(
        "mma.sync.aligned.m16n8k16.row.col.f32.f16.f16.f32 "
        "{%0,%1,%2,%3}, {%4,%5,%6,%7}, {%8,%9}, {%0,%1,%2,%3};"
        : "+f"(d.x), "+f"(d.y), "+f"(d.z), "+f"(d.w)
        : "r"(a0), "r"(a1), "r"(a2), "r"(a3), "r"(b0), "r"(b1));
}

// ---------------- LayerNorm -------------------------------------------------------
__global__ __launch_bounds__(256) void ln_kernel(const float* __restrict__ x,
                                                 const float* __restrict__ gam,
                                                 const float* __restrict__ bet,
                                                 float* __restrict__ out32,
                                                 __half* __restrict__ out16)
{
    const int row = blockIdx.x;
    const int tid = threadIdx.x;
    const float2 v = ((const float2*)(x + (size_t)row * Dd))[tid];
    float s = v.x + v.y, ss = v.x * v.x + v.y * v.y;
    #pragma unroll
    for (int o = 16; o; o >>= 1) {
        s  += __shfl_xor_sync(~0u, s,  o);
        ss += __shfl_xor_sync(~0u, ss, o);
    }
    __shared__ float rs[8], rss[8];
    if ((tid & 31) == 0) { rs[tid >> 5] = s; rss[tid >> 5] = ss; }
    __syncthreads();
    float tot = 0.f, tot2 = 0.f;
    #pragma unroll
    for (int i = 0; i < 8; i++) { tot += rs[i]; tot2 += rss[i]; }
    const float mean = tot * (1.0f / Dd);
    const float var  = tot2 * (1.0f / Dd) - mean * mean;
    const float rstd = rsqrtf(var + 1e-5f);
    const float2 g2 = ((const float2*)gam)[tid];
    const float2 b2 = ((const float2*)bet)[tid];
    float2 o;
    o.x = (v.x - mean) * rstd * g2.x + b2.x;
    o.y = (v.y - mean) * rstd * g2.y + b2.y;
    if (out32) ((float2*)(out32 + (size_t)row * Dd))[tid] = o;
    if (out16) ((__half2*)(out16 + (size_t)row * Dd))[tid] = __floats2half2_rn(o.x, o.y);
}

// ---------------- merged prep -------------------------------------------------------
__global__ __launch_bounds__(256) void prep_kernel(
    const float* __restrict__ wq, const float* __restrict__ wk, const float* __restrict__ wv,
    const float* __restrict__ w1, const float* __restrict__ w2,
    const float* __restrict__ bq, const float* __restrict__ bk, const float* __restrict__ bv,
    __half* __restrict__ wqkvt, __half* __restrict__ w1t, __half* __restrict__ w2t,
    float* __restrict__ bqkv)
{
    const int b = blockIdx.x;
    const int tid = threadIdx.x;
    if (b >= 2816) {
        const int i = (b - 2816) * 256 + tid;
        if (i < 512) bqkv[i] = bq[i];
        else if (i < 1024) bqkv[i] = bk[i - 512];
        else if (i < 1536) bqkv[i] = bv[i - 1024];
        return;
    }
    const float* W; __half* Wt; int K, N, n0, k0;
    if (b < 768) {
        const int which = b >> 8, t = b & 255;
        W = which == 0 ? wq : (which == 1 ? wk : wv);
        Wt = wqkvt + (size_t)which * Dd * Dd;
        K = Dd; N = Dd;
        n0 = (t & 15) * 32; k0 = (t >> 4) * 32;
    } else if (b < 1792) {
        const int t = b - 768;
        W = w1; Wt = w1t; K = Dd; N = FFNf;
        n0 = (t & 63) * 32; k0 = (t >> 6) * 32;
    } else {
        const int t = b - 1792;
        W = w2; Wt = w2t; K = FFNf; N = Dd;
        n0 = (t & 15) * 32; k0 = (t >> 4) * 32;
    }
    __shared__ float t[32][33];
    const int tx = tid & 31, ty = tid >> 5;
    #pragma unroll
    for (int i = 0; i < 32; i += 8) t[ty + i][tx] = W[(size_t)(k0 + ty + i) * N + n0 + tx];
    __syncthreads();
    #pragma unroll
    for (int i = 0; i < 32; i += 8)
        Wt[(size_t)(n0 + ty + i) * K + k0 + tx] = __float2half_rn(t[tx][ty + i]);
}

// ---------------- fp16 warp-MMA GEMM, 3-stage single-sync pipeline -----------------
// MODE 0: write fp16 C16   MODE 1: qkv scatter fp16 (N=1536)   MODE 2: fp32 +res
template<int MODE>
__global__ __launch_bounds__(256, 2) void mma_gemm(const __half* __restrict__ A,
                                                   const __half* __restrict__ Bt,
                                                   const float* __restrict__ bias,
                                                   const float* __restrict__ res,
                                                   float* __restrict__ C,
                                                   __half* __restrict__ C16,
                                                   int M, int N, int K)
{
    extern __shared__ __align__(16) char dyn[];
    char* sA = dyn;                       // 3 stages x 10240B
    char* sB = dyn + 3 * SBYTES;

    const int tid  = threadIdx.x;
    const int m0   = blockIdx.y * 128;
    const int n0   = blockIdx.x * 128;
    const int w    = tid >> 5, lane = tid & 31;
    const int wm   = (w & 1) * 64;
    const int wn   = (w >> 1) * 32;
    const int r    = lane >> 2;
    const int c    = lane & 3;
    const int g    = lane >> 3, lr = lane & 7;

    float4 acc[4][4];
    #pragma unroll
    for (int i = 0; i < 4; i++)
        #pragma unroll
        for (int j = 0; j < 4; j++) acc[i][j] = make_float4(0.f, 0.f, 0.f, 0.f);

    const uint32_t sAbase = smem_u32(sA);
    const uint32_t sBbase = smem_u32(sB);

    const int lrow = tid >> 1;
    const int lsel = tid & 1;
    const uint32_t ldst_off = (uint32_t)(lrow * GP + lsel * 32);
    const __half* asrc = A  + (size_t)(m0 + lrow) * K + lsel * 16;
    const __half* bsrc = Bt + (size_t)(n0 + lrow) * K + lsel * 16;

    const uint32_t aoff = (uint32_t)((wm + (g & 1) * 8 + lr) * GP + (g >> 1) * 16);
    const uint32_t boff = (uint32_t)((wn + ((g >> 1) & 1) * 8 + lr) * GP + (g & 1) * 16);

    const int T = K >> 5;

    // prefetch tiles 0,1 into stages 0,1
    #pragma unroll
    for (int p = 0; p < 2; p++) {
        const uint32_t ad = sAbase + p * SBYTES + ldst_off;
        const uint32_t bd = sBbase + p * SBYTES + ldst_off;
        const __half* as = asrc + p * 32;
        const __half* bs = bsrc + p * 32;
        CP16(ad, as); CP16(ad + 16, as + 8);
        CP16(bd, bs); CP16(bd + 16, bs + 8);
        CP_COMMIT();
    }

    int rb = 0, lb = 2;   // read stage, load stage
    for (int t = 0; t < T; t++) {
        CP_WAIT1();                 // tile t arrived
        __syncthreads();            // all warps done reading stage lb (read at t-1)

        if (t + 2 < T) {            // issue tile t+2 into stage lb
            const uint32_t ad = sAbase + lb * SBYTES + ldst_off;
            const uint32_t bd = sBbase + lb * SBYTES + ldst_off;
            const __half* as = asrc + (t + 2) * 32;
            const __half* bs = bsrc + (t + 2) * 32;
            CP16(ad, as); CP16(ad + 16, as + 8);
            CP16(bd, bs); CP16(bd + 16, bs + 8);
        }
        CP_COMMIT();

        const uint32_t sAb = sAbase + rb * SBYTES;
        const uint32_t sBb = sBbase + rb * SBYTES;
        #pragma unroll
        for (int kg = 0; kg < 2; kg++) {
            uint32_t af[4][4];
            #pragma unroll
            for (int mt = 0; mt < 4; mt++)
                LDSM4(af[mt][0], af[mt][1], af[mt][2], af[mt][3],
                      sAb + aoff + (uint32_t)(mt * 16 * GP + kg * 32));
            uint32_t bf[2][4];
            #pragma unroll
            for (int nt2 = 0; nt2 < 2; nt2++)
                LDSM4(bf[nt2][0], bf[nt2][1], bf[nt2][2], bf[nt2][3],
                      sBb + boff + (uint32_t)(nt2 * 16 * GP + kg * 32));
            #pragma unroll
            for (int mt = 0; mt < 4; mt++) {
                #pragma unroll
                for (int nt2 = 0; nt2 < 2; nt2++) {
                    mma16(acc[mt][nt2 * 2],     af[mt][0], af[mt][1], af[mt][2], af[mt][3],
                          bf[nt2][0], bf[nt2][1]);
                    mma16(acc[mt][nt2 * 2 + 1], af[mt][0], af[mt][1], af[mt][2], af[mt][3],
                          bf[nt2][2], bf[nt2][3]);
                }
            }
        }
        rb = (rb == 2) ? 0 : rb + 1;
        lb = (lb == 2) ? 0 : lb + 1;
    }

    #pragma unroll
    for (int mt = 0; mt < 4; mt++) {
        #pragma unroll
        for (int nt = 0; nt < 4; nt++) {
            const int m = m0 + wm + mt * 16 + r;
            const int n = n0 + wn + nt * 8 + c * 2;
            const float2 bv = *(const float2*)&bias[n];
            float2 lo, hi;
            lo.x = acc[mt][nt].x + bv.x;  lo.y = acc[mt][nt].y + bv.y;
            hi.x = acc[mt][nt].z + bv.x;  hi.y = acc[mt][nt].w + bv.y;
            if (MODE == 2) {
                const float2 r0 = *(const float2*)&res[(size_t)m * N + n];
                const float2 r1 = *(const float2*)&res[(size_t)(m + 8) * N + n];
                lo.x += r0.x; lo.y += r0.y;
                hi.x += r1.x; hi.y += r1.y;
            }
            if (MODE == 1) {
                const int which = n >> 9;
                const int nn = n & 511;
                const int hh = nn >> 6, d = nn & 63;
                const int b0i = m >> 11, s0 = m & (Ss - 1);
                const int b1i = (m + 8) >> 11, s1 = (m + 8) & (Ss - 1);
                __half* base = C16 + (size_t)which * ROWS * Dd;
                *(__half2*)&base[((((size_t)b0i * Hh + hh) * Ss) + s0) * DKk + d] =
                    __floats2half2_rn(lo.x, lo.y);
                *(__half2*)&base[((((size_t)b1i * Hh + hh) * Ss) + s1) * DKk + d] =
                    __floats2half2_rn(hi.x, hi.y);
            } else if (MODE == 0) {
                *(__half2*)&C16[(size_t)m * N + n]       = __floats2half2_rn(lo.x, lo.y);
                *(__half2*)&C16[(size_t)(m + 8) * N + n] = __floats2half2_rn(hi.x, hi.y);
            } else {
                *(float2*)&C[(size_t)m * N + n]       = lo;
                *(float2*)&C[(size_t)(m + 8) * N + n] = hi;
            }
        }
    }
}

// ---------------- MMA flash attention, 3-stage single-sync -------------------------
__global__ __launch_bounds__(256, 2) void attn_mma(const __half* __restrict__ qh,
                                                   const __half* __restrict__ kh,
                                                   const __half* __restrict__ vh,
                                                   const float* __restrict__ hin,
                                                   float* __restrict__ out)
{
    extern __shared__ __align__(16) char dyn[];
    char* sK = dyn;                   // 3 stages x 9216B
    char* sV = dyn + 3 * KSTG;

    const int bh  = blockIdx.y;
    const int cs  = blockIdx.x * 128;
    const int tid = threadIdx.x;
    const int w = tid >> 5, lane = tid & 31;
    const int r = lane >> 2;
    const int c = lane & 3;
    const size_t bhS = (size_t)bh * Ss;

    uint32_t qf[4][4];
    {
        const int q0 = cs + w * 16;
        const __half2 scl = __half2half2(__float2half(0.125f));
        #pragma unroll
        for (int ks = 0; ks < 4; ks++) {
            const __half* qp0 = qh + (bhS + q0 + r) * DKk + ks * 16 + c * 2;
            const __half* qp1 = qp0 + 8 * DKk;
            __half2 a0 = __hmul2(*(const __half2*)qp0, scl);
            __half2 a1 = __hmul2(*(const __half2*)qp1, scl);
            __half2 a2 = __hmul2(*(const __half2*)(qp0 + 8), scl);
            __half2 a3 = __hmul2(*(const __half2*)(qp1 + 8), scl);
            qf[ks][0] = *(uint32_t*)&a0; qf[ks][1] = *(uint32_t*)&a1;
            qf[ks][2] = *(uint32_t*)&a2; qf[ks][3] = *(uint32_t*)&a3;
        }
    }

    const int srow = tid >> 2;
    const int soff = (tid & 3) * 16;
    const uint32_t kbase = smem_u32(sK);
    const uint32_t vbase = smem_u32(sV);
    const uint32_t sdoff = (uint32_t)(srow * KVP + soff) * 2;

    int w0 = cs - 512; if (w0 < 0) w0 = 0;
    int w1 = cs + 256; if (w1 > Ss) w1 = Ss;
    const int T = (w1 - w0) >> 6;

    // prefetch tiles 0,1
    #pragma unroll
    for (int p = 0; p < 2; p++) {
        if (p < T) {
            const __half* ksrc = kh + (bhS + w0 + p * 64 + srow) * DKk + soff;
            const __half* vsrc = vh + (bhS + w0 + p * 64 + srow) * DKk + soff;
            const uint32_t kd = kbase + p * KSTG + sdoff;
            const uint32_t vd = vbase + p * KSTG + sdoff;
            CP16(kd, ksrc); CP16(kd + 16, ksrc + 8);
            CP16(vd, vsrc); CP16(vd + 16, vsrc + 8);
        }
        CP_COMMIT();
    }

    float m0 = -1e30f, m1 = -1e30f, l0 = 0.f, l1 = 0.f;
    float4 accO[8];
    #pragma unroll
    for (int i = 0; i < 8; i++) accO[i] = make_float4(0.f, 0.f, 0.f, 0.f);

    const int qk_row = (lane & 7) + ((lane >> 4) & 1) * 8;
    const int qk_col = ((lane >> 3) & 1) * 8;
    const int pv_row = (lane & 7) + ((lane >> 3) & 1) * 8;
    const int pv_col = ((lane >> 4) & 1) * 8;

    int rb = 0, lb = 2;
    for (int t = 0; t < T; t++) {
        CP_WAIT1();
        __syncthreads();

        if (t + 2 < T) {
            const int j0 = w0 + (t + 2) * 64;
            const __half* ksrc = kh + (bhS + j0 + srow) * DKk + soff;
            const __half* vsrc = vh + (bhS + j0 + srow) * DKk + soff;
            const uint32_t kd = kbase + lb * KSTG + sdoff;
            const uint32_t vd = vbase + lb * KSTG + sdoff;
            CP16(kd, ksrc); CP16(kd + 16, ksrc + 8);
            CP16(vd, vsrc); CP16(vd + 16, vsrc + 8);
        }
        CP_COMMIT();

        const uint32_t sKb = kbase + rb * KSTG;
        const uint32_t sVb = vbase + rb * KSTG;

        float4 s[8];
        #pragma unroll
        for (int i = 0; i < 8; i++) s[i] = make_float4(0.f, 0.f, 0.f, 0.f);
        #pragma unroll
        for (int ks = 0; ks < 4; ks++) {
            #pragma unroll
            for (int n2 = 0; n2 < 4; n2++) {
                uint32_t b0, b1, b2, b3;
                const uint32_t a = sKb +
                    (uint32_t)((n2 * 16 + qk_row) * KVP + ks * 16 + qk_col) * 2;
                LDSM4(b0, b1, b2, b3, a);
                mma16(s[2 * n2],     qf[ks][0], qf[ks][1], qf[ks][2], qf[ks][3], b0, b1);
                mma16(s[2 * n2 + 1], qf[ks][0], qf[ks][1], qf[ks][2], qf[ks][3], b2, b3);
            }
        }

        float mt0 = m0, mt1 = m1;
        #pragma unroll
        for (int i = 0; i < 8; i++) {
            mt0 = fmaxf(mt0, fmaxf(s[i].x, s[i].y));
            mt1 = fmaxf(mt1, fmaxf(s[i].z, s[i].w));
        }
        mt0 = fmaxf(mt0, __shfl_xor_sync(~0u, mt0, 1));
        mt0 = fmaxf(mt0, __shfl_xor_sync(~0u, mt0, 2));
        mt1 = fmaxf(mt1, __shfl_xor_sync(~0u, mt1, 1));
        mt1 = fmaxf(mt1, __shfl_xor_sync(~0u, mt1, 2));
        const float al0 = __expf(m0 - mt0);
        const float al1 = __expf(m1 - mt1);
        m0 = mt0; m1 = mt1;
        l0 *= al0; l1 *= al1;
        #pragma unroll
        for (int i = 0; i < 8; i++) {
            accO[i].x *= al0; accO[i].y *= al0;
            accO[i].z *= al1; accO[i].w *= al1;
        }
        float ps0 = 0.f, ps1 = 0.f;
        #pragma unroll
        for (int i = 0; i < 8; i++) {
            s[i].x = __expf(s[i].x - m0); s[i].y = __expf(s[i].y - m0);
            s[i].z = __expf(s[i].z - m1); s[i].w = __expf(s[i].w - m1);
            ps0 += s[i].x + s[i].y;
            ps1 += s[i].z + s[i].w;
        }
        ps0 += __shfl_xor_sync(~0u, ps0, 1); ps0 += __shfl_xor_sync(~0u, ps0, 2);
        ps1 += __shfl_xor_sync(~0u, ps1, 1); ps1 += __shfl_xor_sync(~0u, ps1, 2);
        l0 += ps0; l1 += ps1;

        uint32_t pf[4][4];
        #pragma unroll
        for (int ks = 0; ks < 4; ks++) {
            __half2 h;
            h = __floats2half2_rn(s[2 * ks].x,     s[2 * ks].y);     pf[ks][0] = *(uint32_t*)&h;
            h = __floats2half2_rn(s[2 * ks].z,     s[2 * ks].w);     pf[ks][1] = *(uint32_t*)&h;
            h = __floats2half2_rn(s[2 * ks + 1].x, s[2 * ks + 1].y); pf[ks][2] = *(uint32_t*)&h;
            h = __floats2half2_rn(s[2 * ks + 1].z, s[2 * ks + 1].w); pf[ks][3] = *(uint32_t*)&h;
        }

        #pragma unroll
        for (int ks = 0; ks < 4; ks++) {
            #pragma unroll
            for (int d2 = 0; d2 < 4; d2++) {
                uint32_t b0, b1, b2, b3;
                const uint32_t a = sVb +
                    (uint32_t)((ks * 16 + pv_row) * KVP + d2 * 16 + pv_col) * 2;
                LDSM4T(b0, b1, b2, b3, a);
                mma16(accO[2 * d2],     pf[ks][0], pf[ks][1], pf[ks][2], pf[ks][3], b0, b1);
                mma16(accO[2 * d2 + 1], pf[ks][0], pf[ks][1], pf[ks][2], pf[ks][3], b2, b3);
            }
        }

        rb = (rb == 2) ? 0 : rb + 1;
        lb = (lb == 2) ? 0 : lb + 1;
    }

    const float inv0 = 1.0f / l0;
    const float inv1 = 1.0f / l1;
    const int b = bh >> 3, head = bh & 7;
    const int q0 = cs + w * 16;
    const size_t base0 = ((size_t)b * Ss + q0 + r) * Dd + head * DKk;
    const size_t base1 = base0 + 8 * Dd;
    #pragma unroll
    for (int dn = 0; dn < 8; dn++) {
        const int d = dn * 8 + c * 2;
        const float2 h0 = *(const float2*)&hin[base0 + d];
        const float2 h1 = *(const float2*)&hin[base1 + d];
        float2 o0, o1;
        o0.x = accO[dn].x * inv0 + h0.x;  o0.y = accO[dn].y * inv0 + h0.y;
        o1.x = accO[dn].z * inv1 + h1.x;  o1.y = accO[dn].w * inv1 + h1.y;
        *(float2*)&out[base0 + d] = o0;
        *(float2*)&out[base1 + d] = o1;
    }
}

// ---------------- launch ------------------------------------------------------------
extern "C" void kernel_launch(void* const* d_in, const int* in_sizes, int n_in,
                              void* d_out, int out_size)
{
    const float* x       = (const float*)d_in[0];
    const float* ln_in_g = (const float*)d_in[2];
    const float* ln_in_b = (const float*)d_in[3];
    const float* wq = (const float*)d_in[4];  const float* bq = (const float*)d_in[5];
    const float* wk = (const float*)d_in[6];  const float* bk = (const float*)d_in[7];
    const float* wv = (const float*)d_in[8];  const float* bv = (const float*)d_in[9];
    const float* ln1_g = (const float*)d_in[10]; const float* ln1_b = (const float*)d_in[11];
    const float* w1 = (const float*)d_in[12]; const float* b1 = (const float*)d_in[13];
    const float* w2 = (const float*)d_in[14]; const float* b2 = (const float*)d_in[15];
    const float* ln2_g = (const float*)d_in[16]; const float* ln2_b = (const float*)d_in[17];
    float* out = (float*)d_out;

    float *ph, *pattn, *pr, *pbqkv;
    __half *ph16, *pqkv16, *po16, *pf16, *pwqkvt, *pw1t, *pw2t;
    cudaGetSymbolAddress((void**)&ph,     g_h);
    cudaGetSymbolAddress((void**)&ph16,   g_h16);
    cudaGetSymbolAddress((void**)&pqkv16, g_qkv16);
    cudaGetSymbolAddress((void**)&pattn,  g_attn);
    cudaGetSymbolAddress((void**)&po16,   g_o16);
    cudaGetSymbolAddress((void**)&pf16,   g_f16);
    cudaGetSymbolAddress((void**)&pr,     g_r);
    cudaGetSymbolAddress((void**)&pwqkvt, g_wqkvt);
    cudaGetSymbolAddress((void**)&pw1t,   g_w1t);
    cudaGetSymbolAddress((void**)&pw2t,   g_w2t);
    cudaGetSymbolAddress((void**)&pbqkv,  g_bqkv);

    // opt-in >48KB dynamic smem (idempotent)
    cudaFuncSetAttribute(mma_gemm<0>, cudaFuncAttributeMaxDynamicSharedMemorySize, GEMM_SMEM);
    cudaFuncSetAttribute(mma_gemm<1>, cudaFuncAttributeMaxDynamicSharedMemorySize, GEMM_SMEM);
    cudaFuncSetAttribute(mma_gemm<2>, cudaFuncAttributeMaxDynamicSharedMemorySize, GEMM_SMEM);
    cudaFuncSetAttribute(attn_mma,    cudaFuncAttributeMaxDynamicSharedMemorySize, ATTN_SMEM);

    // 0. merged prep
    prep_kernel<<<2822, 256>>>(wq, wk, wv, w1, w2, bq, bk, bv,
                               pwqkvt, pw1t, pw2t, pbqkv);

    // 1. h = LN(x)
    ln_kernel<<<ROWS, 256>>>(x, ln_in_g, ln_in_b, ph, ph16);

    // 2. fused QKV (fp16 out)
    mma_gemm<1><<<dim3(12, 64), 256, GEMM_SMEM>>>(ph16, pwqkvt, pbqkv, nullptr, nullptr,
                                                  pqkv16, ROWS, 3 * Dd, Dd);

    // 3. MMA flash attention + residual h
    attn_mma<<<dim3(Ss / 128, Bb * Hh), 256, ATTN_SMEM>>>(pqkv16,
                                                          pqkv16 + (size_t)ROWS * Dd,
                                                          pqkv16 + 2 * (size_t)ROWS * Dd,
                                                          ph, pattn);

    // 4. LN1 -> fp16 only
    ln_kernel<<<ROWS, 256>>>(pattn, ln1_g, ln1_b, nullptr, po16);

    // 5. FFN
    mma_gemm<0><<<dim3(FFNf / 128, 64), 256, GEMM_SMEM>>>(po16, pw1t, b1, nullptr, nullptr,
                                                          pf16, ROWS, FFNf, Dd);
    mma_gemm<2><<<dim3(Dd / 128, 64), 256, GEMM_SMEM>>>(pf16, pw2t, b2, pattn, pr, nullptr,
                                                        ROWS, Dd, FFNf);

    // 6. out = LN2 (fp32 only)
    ln_kernel<<<ROWS, 256>>>(pr, ln2_g, ln2_b, out, nullptr);
}